// round 5
// baseline (speedup 1.0000x reference)
#include <cuda_runtime.h>
#include <cstdint>

#define MAXN  100000
#define MAXE  2000000
#define DH    256
#define DIN   128

// Scratch (static device globals — no allocation allowed)
__device__ float g_dinv[MAXN];
__device__ float g_buf1[(size_t)MAXN * DH];
__device__ float g_buf2[(size_t)MAXN * DH];
__device__ int   g_cnt[MAXN];
__device__ int   g_off[MAXN + 1];
__device__ int   g_cur[MAXN];
__device__ int   g_src[MAXE];

// ---------------------------------------------------------------------------
// CSR build: indegree count
// ---------------------------------------------------------------------------
__global__ void count_kernel(const int* __restrict__ edst, int e, int* __restrict__ cnt) {
    int i = blockIdx.x * blockDim.x + threadIdx.x;
    if (i < e) atomicAdd(&cnt[edst[i]], 1);
}

// Single-block chunked exclusive scan over cnt[0..n) -> off, cursor; also dinv.
__global__ void __launch_bounds__(1024)
scan_kernel(const int* __restrict__ cnt, int* __restrict__ off, int* __restrict__ cur,
            float* __restrict__ dinv, int n) {
    __shared__ int ssum[1024];
    const int tid = threadIdx.x;
    const int chunk = (n + 1023) >> 10;
    const int begin = tid * chunk;
    const int end   = min(begin + chunk, n);

    int mysum = 0;
    for (int i = begin; i < end; i++) mysum += cnt[i];
    ssum[tid] = mysum;
    __syncthreads();

    for (int d = 1; d < 1024; d <<= 1) {
        int add = (tid >= d) ? ssum[tid - d] : 0;
        __syncthreads();
        ssum[tid] += add;
        __syncthreads();
    }

    int run = ssum[tid] - mysum;  // exclusive base for this chunk
    for (int i = begin; i < end; i++) {
        int c = cnt[i];
        off[i] = run;
        cur[i] = run;
        dinv[i] = rsqrtf(1.0f + (float)c);
        run += c;
    }
    if (tid == 1023) off[n] = ssum[1023];
}

__global__ void fill_kernel(const int* __restrict__ esrc, const int* __restrict__ edst,
                            int e, int* __restrict__ cur, int* __restrict__ sorted) {
    int i = blockIdx.x * blockDim.x + threadIdx.x;
    if (i < e) {
        int d = edst[i];
        int pos = atomicAdd(&cur[d], 1);
        sorted[pos] = esrc[i];
    }
}

// ---------------------------------------------------------------------------
// SGEMM with fused row scaling:  C[m, :] = dinv[m] * (A[m, :] @ W)
// BM=128, BN=128, BK=16, 256 threads, 8x8/thread.
// Double-buffered (cp.async for B, register prefetch for A).
// Inner product uses packed fma.rn.f32x2 (FFMA2): 2 fp32 FMAs / issue slot.
// ---------------------------------------------------------------------------
#define BM 128
#define BN 128
#define BK 16
#define AS_STRIDE 132

__device__ __forceinline__ void cp_async16(void* smem_dst, const void* gmem_src) {
    uint32_t s = (uint32_t)__cvta_generic_to_shared(smem_dst);
    asm volatile("cp.async.cg.shared.global [%0], [%1], 16;\n" :: "r"(s), "l"(gmem_src));
}
__device__ __forceinline__ void cp_async_commit() {
    asm volatile("cp.async.commit_group;\n");
}
__device__ __forceinline__ void cp_async_wait0() {
    asm volatile("cp.async.wait_group 0;\n" ::: "memory");
}

__device__ __forceinline__ uint64_t pack2(float lo, float hi) {
    uint64_t r;
    asm("mov.b64 %0, {%1, %2};" : "=l"(r) : "f"(lo), "f"(hi));
    return r;
}
__device__ __forceinline__ uint64_t dup2(float v) {
    uint64_t r;
    asm("mov.b64 %0, {%1, %1};" : "=l"(r) : "f"(v));
    return r;
}
__device__ __forceinline__ void unpack2(uint64_t p, float& lo, float& hi) {
    asm("mov.b64 {%0, %1}, %2;" : "=f"(lo), "=f"(hi) : "l"(p));
}
__device__ __forceinline__ void ffma2(uint64_t& acc, uint64_t a, uint64_t b) {
    asm("fma.rn.f32x2 %0, %1, %2, %0;" : "+l"(acc) : "l"(a), "l"(b));
}

template <int K>
__global__ void __launch_bounds__(256, 2)
gemm_scaled_kernel(const float* __restrict__ A, const float* __restrict__ W,
                   const float* __restrict__ dinv, float* __restrict__ C, int M) {
    constexpr int NT = K / BK;
    __shared__ float As[2][BK * AS_STRIDE];
    __shared__ float Bs[2][BK * BN];

    const int bm  = blockIdx.x * BM;
    const int bn  = blockIdx.y * BN;
    const int tid = threadIdx.x;
    const int tx  = tid & 15;
    const int ty  = tid >> 4;
    const int tm  = ty * 8;
    const int tn  = tx * 8;

    const int arow  = tid >> 1;
    const int acol  = (tid & 1) * 8;
    const int garow = bm + arow;
    const bool arow_ok = (garow < M);
    const float* aptr = arow_ok ? &A[(size_t)garow * K + acol] : nullptr;

    const int brow0 = tid >> 5;           // 0..7
    const int bc0   = (tid & 31) * 4;     // 0..124
    const int brow1 = brow0 + 8;          // 8..15
    const float* wptr0 = &W[(size_t)brow0 * DH + bn + bc0];
    const float* wptr1 = &W[(size_t)brow1 * DH + bn + bc0];

    // acc2[p][j] = packed (row 2p, row 2p+1) for column j
    uint64_t acc2[4][8];
    const uint64_t z2 = dup2(0.0f);
#pragma unroll
    for (int p = 0; p < 4; p++)
#pragma unroll
        for (int j = 0; j < 8; j++) acc2[p][j] = z2;

    // ---- prologue: tile 0 ----
    {
        float4 av0 = make_float4(0.f, 0.f, 0.f, 0.f);
        float4 av1 = make_float4(0.f, 0.f, 0.f, 0.f);
        if (arow_ok) {
            av0 = *reinterpret_cast<const float4*>(aptr);
            av1 = *reinterpret_cast<const float4*>(aptr + 4);
        }
        float* as = &As[0][0];
        as[(acol + 0) * AS_STRIDE + arow] = av0.x;
        as[(acol + 1) * AS_STRIDE + arow] = av0.y;
        as[(acol + 2) * AS_STRIDE + arow] = av0.z;
        as[(acol + 3) * AS_STRIDE + arow] = av0.w;
        as[(acol + 4) * AS_STRIDE + arow] = av1.x;
        as[(acol + 5) * AS_STRIDE + arow] = av1.y;
        as[(acol + 6) * AS_STRIDE + arow] = av1.z;
        as[(acol + 7) * AS_STRIDE + arow] = av1.w;
        cp_async16(&Bs[0][brow0 * BN + bc0], wptr0);
        cp_async16(&Bs[0][brow1 * BN + bc0], wptr1);
        cp_async_commit();
        cp_async_wait0();
        __syncthreads();
    }

    for (int t = 0; t < NT; t++) {
        const int curb = t & 1;
        const int nxtb = curb ^ 1;
        float4 av0, av1;
        const bool has_next = (t + 1 < NT);

        if (has_next) {
            const int k0 = (t + 1) * BK;
            av0 = make_float4(0.f, 0.f, 0.f, 0.f);
            av1 = make_float4(0.f, 0.f, 0.f, 0.f);
            if (arow_ok) {
                av0 = *reinterpret_cast<const float4*>(aptr + k0);
                av1 = *reinterpret_cast<const float4*>(aptr + k0 + 4);
            }
            cp_async16(&Bs[nxtb][brow0 * BN + bc0], wptr0 + (size_t)k0 * DH);
            cp_async16(&Bs[nxtb][brow1 * BN + bc0], wptr1 + (size_t)k0 * DH);
            cp_async_commit();
        }

        const float* as = &As[curb][0];
        const float* bs = &Bs[curb][0];
#pragma unroll
        for (int k = 0; k < BK; k++) {
            float a[8], b[8];
            *reinterpret_cast<float4*>(&a[0]) = *reinterpret_cast<const float4*>(&as[k * AS_STRIDE + tm]);
            *reinterpret_cast<float4*>(&a[4]) = *reinterpret_cast<const float4*>(&as[k * AS_STRIDE + tm + 4]);
            *reinterpret_cast<float4*>(&b[0]) = *reinterpret_cast<const float4*>(&bs[k * BN + tn]);
            *reinterpret_cast<float4*>(&b[4]) = *reinterpret_cast<const float4*>(&bs[k * BN + tn + 4]);

            uint64_t ap[4];
            ap[0] = pack2(a[0], a[1]);
            ap[1] = pack2(a[2], a[3]);
            ap[2] = pack2(a[4], a[5]);
            ap[3] = pack2(a[6], a[7]);
            uint64_t bb[8];
#pragma unroll
            for (int j = 0; j < 8; j++) bb[j] = dup2(b[j]);
#pragma unroll
            for (int p = 0; p < 4; p++)
#pragma unroll
                for (int j = 0; j < 8; j++)
                    ffma2(acc2[p][j], ap[p], bb[j]);
        }

        if (has_next) {
            float* asn = &As[nxtb][0];
            asn[(acol + 0) * AS_STRIDE + arow] = av0.x;
            asn[(acol + 1) * AS_STRIDE + arow] = av0.y;
            asn[(acol + 2) * AS_STRIDE + arow] = av0.z;
            asn[(acol + 3) * AS_STRIDE + arow] = av0.w;
            asn[(acol + 4) * AS_STRIDE + arow] = av1.x;
            asn[(acol + 5) * AS_STRIDE + arow] = av1.y;
            asn[(acol + 6) * AS_STRIDE + arow] = av1.z;
            asn[(acol + 7) * AS_STRIDE + arow] = av1.w;
            cp_async_wait0();
            __syncthreads();
        }
    }

    // ---- epilogue: unpack pairs and store scaled rows ----
#pragma unroll
    for (int p = 0; p < 4; p++) {
        float lo[8], hi[8];
#pragma unroll
        for (int j = 0; j < 8; j++) unpack2(acc2[p][j], lo[j], hi[j]);

        int r0 = bm + tm + 2 * p;
        if (r0 < M) {
            float s = dinv[r0];
            float4 v0 = make_float4(lo[0] * s, lo[1] * s, lo[2] * s, lo[3] * s);
            float4 v1 = make_float4(lo[4] * s, lo[5] * s, lo[6] * s, lo[7] * s);
            float* cp = &C[(size_t)r0 * DH + bn + tn];
            *reinterpret_cast<float4*>(cp)     = v0;
            *reinterpret_cast<float4*>(cp + 4) = v1;
        }
        int r1 = r0 + 1;
        if (r1 < M) {
            float s = dinv[r1];
            float4 v0 = make_float4(hi[0] * s, hi[1] * s, hi[2] * s, hi[3] * s);
            float4 v1 = make_float4(hi[4] * s, hi[5] * s, hi[6] * s, hi[7] * s);
            float* cp = &C[(size_t)r1 * DH + bn + tn];
            *reinterpret_cast<float4*>(cp)     = v0;
            *reinterpret_cast<float4*>(cp + 4) = v1;
        }
    }
}

// ---------------------------------------------------------------------------
// Gather (CSR by destination) + self-loop + finalize:
//   out[d, :] = relu((hp[d, :] + sum_{s in N(d)} hp[s, :]) * dinv[d] + b)
// One warp per destination node; each lane owns 2 float4 (8 floats).
// ---------------------------------------------------------------------------
__global__ void __launch_bounds__(256)
gather_kernel(const float* __restrict__ hp, const int* __restrict__ off,
              const int* __restrict__ sorted, const float* __restrict__ dinv,
              const float* __restrict__ b, float* __restrict__ out, int n) {
    int warp = (blockIdx.x * blockDim.x + threadIdx.x) >> 5;
    int lane = threadIdx.x & 31;
    if (warp >= n) return;
    const int d  = warp;
    const int s0 = off[d];
    const int s1 = off[d + 1];

    const float4* self = reinterpret_cast<const float4*>(hp + (size_t)d * DH) + lane;
    float4 v0 = __ldg(self);
    float4 v1 = __ldg(self + 32);

    int j = s0;
    int snext = (j < s1) ? __ldg(&sorted[j]) : 0;
    for (; j < s1; j++) {
        int s = snext;
        if (j + 1 < s1) snext = __ldg(&sorted[j + 1]);
        const float4* in = reinterpret_cast<const float4*>(hp + (size_t)s * DH) + lane;
        float4 a = __ldg(in);
        float4 c = __ldg(in + 32);
        v0.x += a.x; v0.y += a.y; v0.z += a.z; v0.w += a.w;
        v1.x += c.x; v1.y += c.y; v1.z += c.z; v1.w += c.w;
    }

    const float sc = dinv[d];
    const float4 bb0 = __ldg(reinterpret_cast<const float4*>(b) + lane);
    const float4 bb1 = __ldg(reinterpret_cast<const float4*>(b) + lane + 32);
    v0.x = fmaxf(fmaf(v0.x, sc, bb0.x), 0.0f);
    v0.y = fmaxf(fmaf(v0.y, sc, bb0.y), 0.0f);
    v0.z = fmaxf(fmaf(v0.z, sc, bb0.z), 0.0f);
    v0.w = fmaxf(fmaf(v0.w, sc, bb0.w), 0.0f);
    v1.x = fmaxf(fmaf(v1.x, sc, bb1.x), 0.0f);
    v1.y = fmaxf(fmaf(v1.y, sc, bb1.y), 0.0f);
    v1.z = fmaxf(fmaf(v1.z, sc, bb1.z), 0.0f);
    v1.w = fmaxf(fmaf(v1.w, sc, bb1.w), 0.0f);

    float4* op = reinterpret_cast<float4*>(out + (size_t)d * DH) + lane;
    op[0]  = v0;
    op[32] = v1;
}

// ---------------------------------------------------------------------------
// Launch
// ---------------------------------------------------------------------------
extern "C" void kernel_launch(void* const* d_in, const int* in_sizes, int n_in,
                              void* d_out, int out_size) {
    const float* x  = (const float*)d_in[0];
    const int*   ei = (const int*)d_in[1];
    const float* W1 = (const float*)d_in[2];
    const float* b1 = (const float*)d_in[3];
    const float* W2 = (const float*)d_in[4];
    const float* b2 = (const float*)d_in[5];
    float* out = (float*)d_out;

    const int n = in_sizes[0] / DIN;
    const int e = in_sizes[1] / 2;
    const int* esrc = ei;
    const int* edst = ei + e;

    float *dinv, *buf1, *buf2;
    int *cnt, *off, *cur, *srt;
    cudaGetSymbolAddress((void**)&dinv, g_dinv);
    cudaGetSymbolAddress((void**)&buf1, g_buf1);
    cudaGetSymbolAddress((void**)&buf2, g_buf2);
    cudaGetSymbolAddress((void**)&cnt,  g_cnt);
    cudaGetSymbolAddress((void**)&off,  g_off);
    cudaGetSymbolAddress((void**)&cur,  g_cur);
    cudaGetSymbolAddress((void**)&srt,  g_src);

    const int T = 256;
    const int e_blk = (e + T - 1) / T;
    const int g_blk = (n + (T / 32) - 1) / (T / 32);
    dim3 gemm_grid((n + BM - 1) / BM, DH / BN);

    // ----- CSR build (once, reused by both layers) -----
    cudaMemsetAsync(cnt, 0, (size_t)n * sizeof(int));
    count_kernel<<<e_blk, T>>>(edst, e, cnt);
    scan_kernel<<<1, 1024>>>(cnt, off, cur, dinv, n);
    fill_kernel<<<e_blk, T>>>(esrc, edst, e, cur, srt);

    // ----- Layer 1 -----
    gemm_scaled_kernel<DIN><<<gemm_grid, T>>>(x, W1, dinv, buf1, n);
    gather_kernel<<<g_blk, T>>>(buf1, off, srt, dinv, b1, buf2, n);

    // ----- Layer 2 -----
    gemm_scaled_kernel<DH><<<gemm_grid, T>>>(buf2, W2, dinv, buf1, n);
    gather_kernel<<<g_blk, T>>>(buf1, off, srt, dinv, b2, out, n);
}

// round 6
// speedup vs baseline: 1.0346x; 1.0346x over previous
#include <cuda_runtime.h>
#include <cstdint>

#define MAXN  100000
#define MAXE  2000000
#define DH    256
#define DIN   128

// Scratch (static device globals — no allocation allowed)
__device__ float g_dinv[MAXN];
__device__ float g_buf1[(size_t)MAXN * DH];
__device__ float g_buf2[(size_t)MAXN * DH];
__device__ int   g_cnt[MAXN];
__device__ int   g_off[MAXN + 1];
__device__ int   g_cur[MAXN];
__device__ int   g_src[MAXE];

// ---------------------------------------------------------------------------
// CSR build
// ---------------------------------------------------------------------------
__global__ void count_kernel(const int* __restrict__ edst, int e, int* __restrict__ cnt) {
    int i = blockIdx.x * blockDim.x + threadIdx.x;
    if (i < e) atomicAdd(&cnt[edst[i]], 1);
}

__global__ void __launch_bounds__(1024)
scan_kernel(const int* __restrict__ cnt, int* __restrict__ off, int* __restrict__ cur,
            float* __restrict__ dinv, int n) {
    __shared__ int ssum[1024];
    const int tid = threadIdx.x;
    const int chunk = (n + 1023) >> 10;
    const int begin = tid * chunk;
    const int end   = min(begin + chunk, n);

    int mysum = 0;
    for (int i = begin; i < end; i++) mysum += cnt[i];
    ssum[tid] = mysum;
    __syncthreads();
    for (int d = 1; d < 1024; d <<= 1) {
        int add = (tid >= d) ? ssum[tid - d] : 0;
        __syncthreads();
        ssum[tid] += add;
        __syncthreads();
    }
    int run = ssum[tid] - mysum;
    for (int i = begin; i < end; i++) {
        int c = cnt[i];
        off[i] = run;
        cur[i] = run;
        dinv[i] = rsqrtf(1.0f + (float)c);
        run += c;
    }
    if (tid == 1023) off[n] = ssum[1023];
}

__global__ void fill_kernel(const int* __restrict__ esrc, const int* __restrict__ edst,
                            int e, int* __restrict__ cur, int* __restrict__ sorted) {
    int i = blockIdx.x * blockDim.x + threadIdx.x;
    if (i < e) {
        int d = edst[i];
        int pos = atomicAdd(&cur[d], 1);
        sorted[pos] = esrc[i];
    }
}

// ---------------------------------------------------------------------------
// SGEMM:  acc = A[m,:] @ W   then epilogue per MODE:
//   MODE 0: C = dinv[m] * relu(acc + b)       (layer-1 transform, pre-scaled out)
//   MODE 1: C = relu(acc + b)                 (layer-2 transform -> final out)
// BM=128, BN=128, BK=16, 256 threads, 8x8/thread, double-buffered.
// ---------------------------------------------------------------------------
#define BM 128
#define BN 128
#define BK 16
#define AS_STRIDE 132

__device__ __forceinline__ void cp_async16(void* smem_dst, const void* gmem_src) {
    uint32_t s = (uint32_t)__cvta_generic_to_shared(smem_dst);
    asm volatile("cp.async.cg.shared.global [%0], [%1], 16;\n" :: "r"(s), "l"(gmem_src));
}
__device__ __forceinline__ void cp_async_commit() {
    asm volatile("cp.async.commit_group;\n");
}
__device__ __forceinline__ void cp_async_wait0() {
    asm volatile("cp.async.wait_group 0;\n" ::: "memory");
}

template <int K, int MODE>
__global__ void __launch_bounds__(256, 2)
gemm_kernel(const float* __restrict__ A, const float* __restrict__ W,
            const float* __restrict__ dinv, const float* __restrict__ bias,
            float* __restrict__ C, int M) {
    constexpr int NT = K / BK;
    __shared__ float As[2][BK * AS_STRIDE];
    __shared__ float Bs[2][BK * BN];

    const int bm  = blockIdx.x * BM;
    const int bn  = blockIdx.y * BN;
    const int tid = threadIdx.x;
    const int tx  = tid & 15;
    const int ty  = tid >> 4;
    const int tm  = ty * 8;
    const int tn  = tx * 8;

    const int arow  = tid >> 1;
    const int acol  = (tid & 1) * 8;
    const int garow = bm + arow;
    const bool arow_ok = (garow < M);
    const float* aptr = arow_ok ? &A[(size_t)garow * K + acol] : nullptr;

    const int brow0 = tid >> 5;
    const int bc0   = (tid & 31) * 4;
    const int brow1 = brow0 + 8;
    const float* wptr0 = &W[(size_t)brow0 * DH + bn + bc0];
    const float* wptr1 = &W[(size_t)brow1 * DH + bn + bc0];

    float acc[8][8];
#pragma unroll
    for (int i = 0; i < 8; i++)
#pragma unroll
        for (int j = 0; j < 8; j++) acc[i][j] = 0.0f;

    // prologue
    {
        float4 av0 = make_float4(0.f, 0.f, 0.f, 0.f);
        float4 av1 = make_float4(0.f, 0.f, 0.f, 0.f);
        if (arow_ok) {
            av0 = *reinterpret_cast<const float4*>(aptr);
            av1 = *reinterpret_cast<const float4*>(aptr + 4);
        }
        float* as = &As[0][0];
        as[(acol + 0) * AS_STRIDE + arow] = av0.x;
        as[(acol + 1) * AS_STRIDE + arow] = av0.y;
        as[(acol + 2) * AS_STRIDE + arow] = av0.z;
        as[(acol + 3) * AS_STRIDE + arow] = av0.w;
        as[(acol + 4) * AS_STRIDE + arow] = av1.x;
        as[(acol + 5) * AS_STRIDE + arow] = av1.y;
        as[(acol + 6) * AS_STRIDE + arow] = av1.z;
        as[(acol + 7) * AS_STRIDE + arow] = av1.w;
        cp_async16(&Bs[0][brow0 * BN + bc0], wptr0);
        cp_async16(&Bs[0][brow1 * BN + bc0], wptr1);
        cp_async_commit();
        cp_async_wait0();
        __syncthreads();
    }

    for (int t = 0; t < NT; t++) {
        const int curb = t & 1;
        const int nxtb = curb ^ 1;
        float4 av0, av1;
        const bool has_next = (t + 1 < NT);

        if (has_next) {
            const int k0 = (t + 1) * BK;
            av0 = make_float4(0.f, 0.f, 0.f, 0.f);
            av1 = make_float4(0.f, 0.f, 0.f, 0.f);
            if (arow_ok) {
                av0 = *reinterpret_cast<const float4*>(aptr + k0);
                av1 = *reinterpret_cast<const float4*>(aptr + k0 + 4);
            }
            cp_async16(&Bs[nxtb][brow0 * BN + bc0], wptr0 + (size_t)k0 * DH);
            cp_async16(&Bs[nxtb][brow1 * BN + bc0], wptr1 + (size_t)k0 * DH);
            cp_async_commit();
        }

        const float* as = &As[curb][0];
        const float* bs = &Bs[curb][0];
#pragma unroll
        for (int k = 0; k < BK; k++) {
            float a[8], b[8];
            *reinterpret_cast<float4*>(&a[0]) = *reinterpret_cast<const float4*>(&as[k * AS_STRIDE + tm]);
            *reinterpret_cast<float4*>(&a[4]) = *reinterpret_cast<const float4*>(&as[k * AS_STRIDE + tm + 4]);
            *reinterpret_cast<float4*>(&b[0]) = *reinterpret_cast<const float4*>(&bs[k * BN + tn]);
            *reinterpret_cast<float4*>(&b[4]) = *reinterpret_cast<const float4*>(&bs[k * BN + tn + 4]);
#pragma unroll
            for (int i = 0; i < 8; i++)
#pragma unroll
                for (int j = 0; j < 8; j++)
                    acc[i][j] = fmaf(a[i], b[j], acc[i][j]);
        }

        if (has_next) {
            float* asn = &As[nxtb][0];
            asn[(acol + 0) * AS_STRIDE + arow] = av0.x;
            asn[(acol + 1) * AS_STRIDE + arow] = av0.y;
            asn[(acol + 2) * AS_STRIDE + arow] = av0.z;
            asn[(acol + 3) * AS_STRIDE + arow] = av0.w;
            asn[(acol + 4) * AS_STRIDE + arow] = av1.x;
            asn[(acol + 5) * AS_STRIDE + arow] = av1.y;
            asn[(acol + 6) * AS_STRIDE + arow] = av1.z;
            asn[(acol + 7) * AS_STRIDE + arow] = av1.w;
            cp_async_wait0();
            __syncthreads();
        }
    }

    // epilogue
    float bb[8];
    *reinterpret_cast<float4*>(&bb[0]) = *reinterpret_cast<const float4*>(&bias[bn + tn]);
    *reinterpret_cast<float4*>(&bb[4]) = *reinterpret_cast<const float4*>(&bias[bn + tn + 4]);

#pragma unroll
    for (int i = 0; i < 8; i++) {
        int r = bm + tm + i;
        if (r < M) {
            float v[8];
#pragma unroll
            for (int j = 0; j < 8; j++) v[j] = fmaxf(acc[i][j] + bb[j], 0.0f);
            if (MODE == 0) {
                float s = dinv[r];
#pragma unroll
                for (int j = 0; j < 8; j++) v[j] *= s;
            }
            float* cp = &C[(size_t)r * DH + bn + tn];
            *reinterpret_cast<float4*>(cp)     = *reinterpret_cast<float4*>(&v[0]);
            *reinterpret_cast<float4*>(cp + 4) = *reinterpret_cast<float4*>(&v[4]);
        }
    }
}

// ---------------------------------------------------------------------------
// Gather layer 1 (128-dim raw features, per-src dinv applied inline):
//   z1[d] = dinv[d] * ( sum_{s in N(d)} dinv[s]*x[s]  +  dinv[d]*x[d] )
// One warp per node; lane owns one float4 (32*4 = 128).
// ---------------------------------------------------------------------------
__global__ void __launch_bounds__(256)
gather_x_kernel(const float* __restrict__ x, const int* __restrict__ off,
                const int* __restrict__ sorted, const float* __restrict__ dinv,
                float* __restrict__ z, int n) {
    int warp = (blockIdx.x * blockDim.x + threadIdx.x) >> 5;
    int lane = threadIdx.x & 31;
    if (warp >= n) return;
    const int d  = warp;
    const int s0 = off[d];
    const int s1 = off[d + 1];
    const float dd = dinv[d];

    float4 a = __ldg(reinterpret_cast<const float4*>(x + (size_t)d * DIN) + lane);
    float4 v = make_float4(a.x * dd, a.y * dd, a.z * dd, a.w * dd);

    int j = s0;
    int snext = (j < s1) ? __ldg(&sorted[j]) : 0;
    for (; j < s1; j++) {
        int s = snext;
        if (j + 1 < s1) snext = __ldg(&sorted[j + 1]);
        float ds = __ldg(&dinv[s]);
        float4 r = __ldg(reinterpret_cast<const float4*>(x + (size_t)s * DIN) + lane);
        v.x = fmaf(r.x, ds, v.x);
        v.y = fmaf(r.y, ds, v.y);
        v.z = fmaf(r.z, ds, v.z);
        v.w = fmaf(r.w, ds, v.w);
    }
    v.x *= dd; v.y *= dd; v.z *= dd; v.w *= dd;
    *(reinterpret_cast<float4*>(z + (size_t)d * DIN) + lane) = v;
}

// ---------------------------------------------------------------------------
// Gather layer 2 (256-dim, inputs pre-scaled by dinv[src]):
//   z2[d] = dinv[d] * ( sum_{s in N(d)} hs[s]  +  hs[d] )
// One warp per node; lane owns 2 float4.
// ---------------------------------------------------------------------------
__global__ void __launch_bounds__(256)
gather_h_kernel(const float* __restrict__ hs, const int* __restrict__ off,
                const int* __restrict__ sorted, const float* __restrict__ dinv,
                float* __restrict__ z, int n) {
    int warp = (blockIdx.x * blockDim.x + threadIdx.x) >> 5;
    int lane = threadIdx.x & 31;
    if (warp >= n) return;
    const int d  = warp;
    const int s0 = off[d];
    const int s1 = off[d + 1];

    const float4* self = reinterpret_cast<const float4*>(hs + (size_t)d * DH) + lane;
    float4 v0 = __ldg(self);
    float4 v1 = __ldg(self + 32);

    int j = s0;
    int snext = (j < s1) ? __ldg(&sorted[j]) : 0;
    for (; j < s1; j++) {
        int s = snext;
        if (j + 1 < s1) snext = __ldg(&sorted[j + 1]);
        const float4* in = reinterpret_cast<const float4*>(hs + (size_t)s * DH) + lane;
        float4 a = __ldg(in);
        float4 c = __ldg(in + 32);
        v0.x += a.x; v0.y += a.y; v0.z += a.z; v0.w += a.w;
        v1.x += c.x; v1.y += c.y; v1.z += c.z; v1.w += c.w;
    }

    const float dd = dinv[d];
    v0.x *= dd; v0.y *= dd; v0.z *= dd; v0.w *= dd;
    v1.x *= dd; v1.y *= dd; v1.z *= dd; v1.w *= dd;

    float4* op = reinterpret_cast<float4*>(z + (size_t)d * DH) + lane;
    op[0]  = v0;
    op[32] = v1;
}

// ---------------------------------------------------------------------------
// Launch
// ---------------------------------------------------------------------------
extern "C" void kernel_launch(void* const* d_in, const int* in_sizes, int n_in,
                              void* d_out, int out_size) {
    const float* x  = (const float*)d_in[0];
    const int*   ei = (const int*)d_in[1];
    const float* W1 = (const float*)d_in[2];
    const float* b1 = (const float*)d_in[3];
    const float* W2 = (const float*)d_in[4];
    const float* b2 = (const float*)d_in[5];
    float* out = (float*)d_out;

    const int n = in_sizes[0] / DIN;
    const int e = in_sizes[1] / 2;
    const int* esrc = ei;
    const int* edst = ei + e;

    float *dinv, *buf1, *buf2;
    int *cnt, *off, *cur, *srt;
    cudaGetSymbolAddress((void**)&dinv, g_dinv);
    cudaGetSymbolAddress((void**)&buf1, g_buf1);
    cudaGetSymbolAddress((void**)&buf2, g_buf2);
    cudaGetSymbolAddress((void**)&cnt,  g_cnt);
    cudaGetSymbolAddress((void**)&off,  g_off);
    cudaGetSymbolAddress((void**)&cur,  g_cur);
    cudaGetSymbolAddress((void**)&srt,  g_src);

    const int T = 256;
    const int e_blk = (e + T - 1) / T;
    const int g_blk = (n + (T / 32) - 1) / (T / 32);
    dim3 gemm_grid((n + BM - 1) / BM, DH / BN);

    // ----- CSR build -----
    cudaMemsetAsync(cnt, 0, (size_t)n * sizeof(int));
    count_kernel<<<e_blk, T>>>(edst, e, cnt);
    scan_kernel<<<1, 1024>>>(cnt, off, cur, dinv, n);
    fill_kernel<<<e_blk, T>>>(esrc, edst, e, cur, srt);

    // ----- Layer 1 (aggregate-first: 128-dim gather) -----
    gather_x_kernel<<<g_blk, T>>>(x, off, srt, dinv, buf1, n);                 // z1 = A_norm x
    gemm_kernel<DIN, 0><<<gemm_grid, T>>>(buf1, W1, dinv, b1, buf2, n);        // hs = dinv*relu(z1@W1+b1)

    // ----- Layer 2 (aggregate-then-transform) -----
    gather_h_kernel<<<g_blk, T>>>(buf2, off, srt, dinv, buf1, n);              // z2 = A_norm-weighted sum
    gemm_kernel<DH, 1><<<gemm_grid, T>>>(buf1, W2, dinv, b2, out, n);          // out = relu(z2@W2+b2)
}

// round 7
// speedup vs baseline: 1.0444x; 1.0095x over previous
#include <cuda_runtime.h>
#include <cstdint>

#define MAXN  100000
#define MAXE  2000000
#define DH    256
#define DIN   128

// Scratch (static device globals — no allocation allowed)
__device__ float g_dinv[MAXN];
__device__ float g_buf1[(size_t)MAXN * DH];
__device__ float g_buf2[(size_t)MAXN * DH];
__device__ int   g_cnt[MAXN];
__device__ int   g_off[MAXN + 1];
__device__ int   g_cur[MAXN];
__device__ int   g_src[MAXE];

// ---------------------------------------------------------------------------
// CSR build
// ---------------------------------------------------------------------------
__global__ void count_kernel(const int* __restrict__ edst, int e, int* __restrict__ cnt) {
    int i = blockIdx.x * blockDim.x + threadIdx.x;
    if (i < e) atomicAdd(&cnt[edst[i]], 1);
}

__global__ void __launch_bounds__(1024)
scan_kernel(const int* __restrict__ cnt, int* __restrict__ off, int* __restrict__ cur,
            float* __restrict__ dinv, int n) {
    __shared__ int ssum[1024];
    const int tid = threadIdx.x;
    const int chunk = (n + 1023) >> 10;
    const int begin = tid * chunk;
    const int end   = min(begin + chunk, n);

    int mysum = 0;
    for (int i = begin; i < end; i++) mysum += cnt[i];
    ssum[tid] = mysum;
    __syncthreads();
    for (int d = 1; d < 1024; d <<= 1) {
        int add = (tid >= d) ? ssum[tid - d] : 0;
        __syncthreads();
        ssum[tid] += add;
        __syncthreads();
    }
    int run = ssum[tid] - mysum;
    for (int i = begin; i < end; i++) {
        int c = cnt[i];
        off[i] = run;
        cur[i] = run;
        dinv[i] = rsqrtf(1.0f + (float)c);
        run += c;
    }
    if (tid == 1023) off[n] = ssum[1023];
}

__global__ void fill_kernel(const int* __restrict__ esrc, const int* __restrict__ edst,
                            int e, int* __restrict__ cur, int* __restrict__ sorted) {
    int i = blockIdx.x * blockDim.x + threadIdx.x;
    if (i < e) {
        int d = edst[i];
        int pos = atomicAdd(&cur[d], 1);
        sorted[pos] = esrc[i];
    }
}

// ---------------------------------------------------------------------------
// SGEMM, full-width N (BN = 256 = DH):  acc = A[m,:] @ W, then epilogue:
//   MODE 0: C = dinv[m] * relu(acc + b)
//   MODE 1: C = relu(acc + b)
// BM=128, BN=256, BK=16, 512 threads, 8x8/thread, double-buffered.
// A is read from DRAM exactly once (single column block).
// ---------------------------------------------------------------------------
#define BM 128
#define BK 16
#define AS_STRIDE 132
#define GEMM_SMEM ((2 * BK * AS_STRIDE + 2 * BK * DH) * 4)

__device__ __forceinline__ void cp_async16(void* smem_dst, const void* gmem_src) {
    uint32_t s = (uint32_t)__cvta_generic_to_shared(smem_dst);
    asm volatile("cp.async.cg.shared.global [%0], [%1], 16;\n" :: "r"(s), "l"(gmem_src));
}
__device__ __forceinline__ void cp_async_commit() {
    asm volatile("cp.async.commit_group;\n");
}
__device__ __forceinline__ void cp_async_wait0() {
    asm volatile("cp.async.wait_group 0;\n" ::: "memory");
}

template <int K, int MODE>
__global__ void __launch_bounds__(512, 1)
gemm_kernel(const float* __restrict__ A, const float* __restrict__ W,
            const float* __restrict__ dinv, const float* __restrict__ bias,
            float* __restrict__ C, int M) {
    constexpr int NT = K / BK;
    extern __shared__ float sm[];
    float* AsBase = sm;                       // 2 * BK * AS_STRIDE
    float* BsBase = sm + 2 * BK * AS_STRIDE;  // 2 * BK * DH

    const int tid = threadIdx.x;
    const int bm  = blockIdx.x * BM;
    const int tx  = tid & 31;    // 0..31 -> col block of 8 (256 cols)
    const int ty  = tid >> 5;    // 0..15 -> row block of 8 (128 rows)
    const int tm  = ty * 8;
    const int tn  = tx * 8;

    // A-tile load: 128 rows x 16 cols = 512 float4; 1 per thread.
    const int arow  = tid >> 2;         // 0..127
    const int acol  = (tid & 3) * 4;    // 0,4,8,12
    const int garow = bm + arow;
    const bool aok  = (garow < M);
    const float* aptr = aok ? &A[(size_t)garow * K + acol] : nullptr;

    // B-tile load: 16 rows x 256 cols = 1024 float4; 2 per thread.
    const int brow0 = tid >> 6;               // 0..7
    const int bc0   = (tid & 63) * 4;         // 0..252
    const int brow1 = (tid + 512) >> 6;       // 8..15
    const float* wp0 = &W[(size_t)brow0 * DH + bc0];
    const float* wp1 = &W[(size_t)brow1 * DH + bc0];

    float acc[8][8];
#pragma unroll
    for (int i = 0; i < 8; i++)
#pragma unroll
        for (int j = 0; j < 8; j++) acc[i][j] = 0.0f;

    // prologue: tile 0
    {
        float4 av = make_float4(0.f, 0.f, 0.f, 0.f);
        if (aok) av = *reinterpret_cast<const float4*>(aptr);
        float* as = AsBase;
        as[(acol + 0) * AS_STRIDE + arow] = av.x;
        as[(acol + 1) * AS_STRIDE + arow] = av.y;
        as[(acol + 2) * AS_STRIDE + arow] = av.z;
        as[(acol + 3) * AS_STRIDE + arow] = av.w;
        cp_async16(&BsBase[brow0 * DH + bc0], wp0);
        cp_async16(&BsBase[brow1 * DH + bc0], wp1);
        cp_async_commit();
        cp_async_wait0();
        __syncthreads();
    }

    for (int t = 0; t < NT; t++) {
        const int curb = t & 1;
        const int nxtb = curb ^ 1;
        const bool has_next = (t + 1 < NT);
        float4 av;

        if (has_next) {
            const int k0 = (t + 1) * BK;
            av = make_float4(0.f, 0.f, 0.f, 0.f);
            if (aok) av = *reinterpret_cast<const float4*>(aptr + k0);
            cp_async16(&BsBase[nxtb * (BK * DH) + brow0 * DH + bc0], wp0 + (size_t)k0 * DH);
            cp_async16(&BsBase[nxtb * (BK * DH) + brow1 * DH + bc0], wp1 + (size_t)k0 * DH);
            cp_async_commit();
        }

        const float* as = AsBase + curb * (BK * AS_STRIDE);
        const float* bs = BsBase + curb * (BK * DH);
#pragma unroll
        for (int k = 0; k < BK; k++) {
            float a[8], b[8];
            *reinterpret_cast<float4*>(&a[0]) = *reinterpret_cast<const float4*>(&as[k * AS_STRIDE + tm]);
            *reinterpret_cast<float4*>(&a[4]) = *reinterpret_cast<const float4*>(&as[k * AS_STRIDE + tm + 4]);
            *reinterpret_cast<float4*>(&b[0]) = *reinterpret_cast<const float4*>(&bs[k * DH + tn]);
            *reinterpret_cast<float4*>(&b[4]) = *reinterpret_cast<const float4*>(&bs[k * DH + tn + 4]);
#pragma unroll
            for (int i = 0; i < 8; i++)
#pragma unroll
                for (int j = 0; j < 8; j++)
                    acc[i][j] = fmaf(a[i], b[j], acc[i][j]);
        }

        if (has_next) {
            float* asn = AsBase + nxtb * (BK * AS_STRIDE);
            asn[(acol + 0) * AS_STRIDE + arow] = av.x;
            asn[(acol + 1) * AS_STRIDE + arow] = av.y;
            asn[(acol + 2) * AS_STRIDE + arow] = av.z;
            asn[(acol + 3) * AS_STRIDE + arow] = av.w;
            cp_async_wait0();
            __syncthreads();
        }
    }

    // epilogue
    float bb[8];
    *reinterpret_cast<float4*>(&bb[0]) = *reinterpret_cast<const float4*>(&bias[tn]);
    *reinterpret_cast<float4*>(&bb[4]) = *reinterpret_cast<const float4*>(&bias[tn + 4]);

#pragma unroll
    for (int i = 0; i < 8; i++) {
        int r = bm + tm + i;
        if (r < M) {
            float v[8];
#pragma unroll
            for (int j = 0; j < 8; j++) v[j] = fmaxf(acc[i][j] + bb[j], 0.0f);
            if (MODE == 0) {
                float s = dinv[r];
#pragma unroll
                for (int j = 0; j < 8; j++) v[j] *= s;
            }
            float* cp = &C[(size_t)r * DH + tn];
            *reinterpret_cast<float4*>(cp)     = *reinterpret_cast<float4*>(&v[0]);
            *reinterpret_cast<float4*>(cp + 4) = *reinterpret_cast<float4*>(&v[4]);
        }
    }
}

// ---------------------------------------------------------------------------
// Gather layer 1 (128-dim raw features), unrolled x2:
//   z1[d] = dinv[d] * ( sum_{s in N(d)} dinv[s]*x[s]  +  dinv[d]*x[d] )
// ---------------------------------------------------------------------------
__global__ void __launch_bounds__(256)
gather_x_kernel(const float* __restrict__ x, const int* __restrict__ off,
                const int* __restrict__ sorted, const float* __restrict__ dinv,
                float* __restrict__ z, int n) {
    int warp = (blockIdx.x * blockDim.x + threadIdx.x) >> 5;
    int lane = threadIdx.x & 31;
    if (warp >= n) return;
    const int d  = warp;
    const int s0 = off[d];
    const int s1 = off[d + 1];
    const float dd = dinv[d];

    float4 a = __ldg(reinterpret_cast<const float4*>(x + (size_t)d * DIN) + lane);
    float4 v = make_float4(a.x * dd, a.y * dd, a.z * dd, a.w * dd);

    int j = s0;
    for (; j + 1 < s1; j += 2) {
        int sA = __ldg(&sorted[j]);
        int sB = __ldg(&sorted[j + 1]);
        float dA = __ldg(&dinv[sA]);
        float dB = __ldg(&dinv[sB]);
        float4 rA = __ldg(reinterpret_cast<const float4*>(x + (size_t)sA * DIN) + lane);
        float4 rB = __ldg(reinterpret_cast<const float4*>(x + (size_t)sB * DIN) + lane);
        v.x = fmaf(rA.x, dA, v.x); v.y = fmaf(rA.y, dA, v.y);
        v.z = fmaf(rA.z, dA, v.z); v.w = fmaf(rA.w, dA, v.w);
        v.x = fmaf(rB.x, dB, v.x); v.y = fmaf(rB.y, dB, v.y);
        v.z = fmaf(rB.z, dB, v.z); v.w = fmaf(rB.w, dB, v.w);
    }
    if (j < s1) {
        int s = __ldg(&sorted[j]);
        float ds = __ldg(&dinv[s]);
        float4 r = __ldg(reinterpret_cast<const float4*>(x + (size_t)s * DIN) + lane);
        v.x = fmaf(r.x, ds, v.x); v.y = fmaf(r.y, ds, v.y);
        v.z = fmaf(r.z, ds, v.z); v.w = fmaf(r.w, ds, v.w);
    }
    v.x *= dd; v.y *= dd; v.z *= dd; v.w *= dd;
    *(reinterpret_cast<float4*>(z + (size_t)d * DIN) + lane) = v;
}

// ---------------------------------------------------------------------------
// Gather layer 2 (256-dim, inputs pre-scaled by dinv[src]), unrolled x2:
//   z2[d] = dinv[d] * ( sum_{s in N(d)} hs[s]  +  hs[d] )
// ---------------------------------------------------------------------------
__global__ void __launch_bounds__(256)
gather_h_kernel(const float* __restrict__ hs, const int* __restrict__ off,
                const int* __restrict__ sorted, const float* __restrict__ dinv,
                float* __restrict__ z, int n) {
    int warp = (blockIdx.x * blockDim.x + threadIdx.x) >> 5;
    int lane = threadIdx.x & 31;
    if (warp >= n) return;
    const int d  = warp;
    const int s0 = off[d];
    const int s1 = off[d + 1];

    const float4* self = reinterpret_cast<const float4*>(hs + (size_t)d * DH) + lane;
    float4 v0 = __ldg(self);
    float4 v1 = __ldg(self + 32);

    int j = s0;
    for (; j + 1 < s1; j += 2) {
        int sA = __ldg(&sorted[j]);
        int sB = __ldg(&sorted[j + 1]);
        const float4* inA = reinterpret_cast<const float4*>(hs + (size_t)sA * DH) + lane;
        const float4* inB = reinterpret_cast<const float4*>(hs + (size_t)sB * DH) + lane;
        float4 a0 = __ldg(inA);
        float4 a1 = __ldg(inA + 32);
        float4 c0 = __ldg(inB);
        float4 c1 = __ldg(inB + 32);
        v0.x += a0.x + c0.x; v0.y += a0.y + c0.y;
        v0.z += a0.z + c0.z; v0.w += a0.w + c0.w;
        v1.x += a1.x + c1.x; v1.y += a1.y + c1.y;
        v1.z += a1.z + c1.z; v1.w += a1.w + c1.w;
    }
    if (j < s1) {
        int s = __ldg(&sorted[j]);
        const float4* in = reinterpret_cast<const float4*>(hs + (size_t)s * DH) + lane;
        float4 a0 = __ldg(in);
        float4 a1 = __ldg(in + 32);
        v0.x += a0.x; v0.y += a0.y; v0.z += a0.z; v0.w += a0.w;
        v1.x += a1.x; v1.y += a1.y; v1.z += a1.z; v1.w += a1.w;
    }

    const float dd = dinv[d];
    v0.x *= dd; v0.y *= dd; v0.z *= dd; v0.w *= dd;
    v1.x *= dd; v1.y *= dd; v1.z *= dd; v1.w *= dd;

    float4* op = reinterpret_cast<float4*>(z + (size_t)d * DH) + lane;
    op[0]  = v0;
    op[32] = v1;
}

// ---------------------------------------------------------------------------
// Launch
// ---------------------------------------------------------------------------
extern "C" void kernel_launch(void* const* d_in, const int* in_sizes, int n_in,
                              void* d_out, int out_size) {
    const float* x  = (const float*)d_in[0];
    const int*   ei = (const int*)d_in[1];
    const float* W1 = (const float*)d_in[2];
    const float* b1 = (const float*)d_in[3];
    const float* W2 = (const float*)d_in[4];
    const float* b2 = (const float*)d_in[5];
    float* out = (float*)d_out;

    const int n = in_sizes[0] / DIN;
    const int e = in_sizes[1] / 2;
    const int* esrc = ei;
    const int* edst = ei + e;

    float *dinv, *buf1, *buf2;
    int *cnt, *off, *cur, *srt;
    cudaGetSymbolAddress((void**)&dinv, g_dinv);
    cudaGetSymbolAddress((void**)&buf1, g_buf1);
    cudaGetSymbolAddress((void**)&buf2, g_buf2);
    cudaGetSymbolAddress((void**)&cnt,  g_cnt);
    cudaGetSymbolAddress((void**)&off,  g_off);
    cudaGetSymbolAddress((void**)&cur,  g_cur);
    cudaGetSymbolAddress((void**)&srt,  g_src);

    static bool attr_done = false;
    if (!attr_done) {
        cudaFuncSetAttribute(gemm_kernel<DIN, 0>, cudaFuncAttributeMaxDynamicSharedMemorySize, GEMM_SMEM);
        cudaFuncSetAttribute(gemm_kernel<DH, 1>,  cudaFuncAttributeMaxDynamicSharedMemorySize, GEMM_SMEM);
        attr_done = true;
    }

    const int T = 256;
    const int e_blk = (e + T - 1) / T;
    const int g_blk = (n + (T / 32) - 1) / (T / 32);
    const int gemm_blk = (n + BM - 1) / BM;

    // ----- CSR build -----
    cudaMemsetAsync(cnt, 0, (size_t)n * sizeof(int));
    count_kernel<<<e_blk, T>>>(edst, e, cnt);
    scan_kernel<<<1, 1024>>>(cnt, off, cur, dinv, n);
    fill_kernel<<<e_blk, T>>>(esrc, edst, e, cur, srt);

    // ----- Layer 1 (aggregate-first: 128-dim gather) -----
    gather_x_kernel<<<g_blk, T>>>(x, off, srt, dinv, buf1, n);                    // z1 = A_norm x
    gemm_kernel<DIN, 0><<<gemm_blk, 512, GEMM_SMEM>>>(buf1, W1, dinv, b1, buf2, n);

    // ----- Layer 2 (aggregate-then-transform) -----
    gather_h_kernel<<<g_blk, T>>>(buf2, off, srt, dinv, buf1, n);                 // z2
    gemm_kernel<DH, 1><<<gemm_blk, 512, GEMM_SMEM>>>(buf1, W2, dinv, b2, out, n);
}

// round 8
// speedup vs baseline: 1.0922x; 1.0458x over previous
#include <cuda_runtime.h>
#include <cstdint>

#define MAXN  100000
#define MAXE  2000000
#define DH    256
#define DIN   128

// Scratch (static device globals — no allocation allowed)
__device__ float g_dinv[MAXN];
__device__ float g_buf1[(size_t)MAXN * DH];
__device__ float g_buf2[(size_t)MAXN * DH];
__device__ int   g_cnt[MAXN];
__device__ int   g_off[MAXN + 1];
__device__ int   g_cur[MAXN];
__device__ int   g_src[MAXE];

// ---------------------------------------------------------------------------
// CSR build
// ---------------------------------------------------------------------------
__global__ void count_kernel(const int* __restrict__ edst, int e, int* __restrict__ cnt) {
    int i = blockIdx.x * blockDim.x + threadIdx.x;
    if (i < e) atomicAdd(&cnt[edst[i]], 1);
}

__global__ void __launch_bounds__(1024)
scan_kernel(const int* __restrict__ cnt, int* __restrict__ off, int* __restrict__ cur,
            float* __restrict__ dinv, int n) {
    __shared__ int ssum[1024];
    const int tid = threadIdx.x;
    const int chunk = (n + 1023) >> 10;
    const int begin = tid * chunk;
    const int end   = min(begin + chunk, n);

    int mysum = 0;
    for (int i = begin; i < end; i++) mysum += cnt[i];
    ssum[tid] = mysum;
    __syncthreads();
    for (int d = 1; d < 1024; d <<= 1) {
        int add = (tid >= d) ? ssum[tid - d] : 0;
        __syncthreads();
        ssum[tid] += add;
        __syncthreads();
    }
    int run = ssum[tid] - mysum;
    for (int i = begin; i < end; i++) {
        int c = cnt[i];
        off[i] = run;
        cur[i] = run;
        dinv[i] = rsqrtf(1.0f + (float)c);
        run += c;
    }
    if (tid == 1023) off[n] = ssum[1023];
}

__global__ void fill_kernel(const int* __restrict__ esrc, const int* __restrict__ edst,
                            int e, int* __restrict__ cur, int* __restrict__ sorted) {
    int i = blockIdx.x * blockDim.x + threadIdx.x;
    if (i < e) {
        int d = edst[i];
        int pos = atomicAdd(&cur[d], 1);
        sorted[pos] = esrc[i];
    }
}

// ---------------------------------------------------------------------------
// SGEMM, full-width N (BN = 256 = DH):  acc = A[m,:] @ W, then epilogue:
//   MODE 0: C = dinv[m] * relu(acc + b)
//   MODE 1: C = relu(acc + b)
// BM=128, BN=256, BK=16, 512 threads, 8x8/thread, double-buffered.
// Per-thread columns split as {tn, tn+128} with tn = tx*4: B-fragment LDS.128
// is conflict-free (16B lane stride -> contiguous 128B per phase).
// ---------------------------------------------------------------------------
#define BM 128
#define BK 16
#define AS_STRIDE 132
#define GEMM_SMEM ((2 * BK * AS_STRIDE + 2 * BK * DH) * 4)

__device__ __forceinline__ void cp_async16(void* smem_dst, const void* gmem_src) {
    uint32_t s = (uint32_t)__cvta_generic_to_shared(smem_dst);
    asm volatile("cp.async.cg.shared.global [%0], [%1], 16;\n" :: "r"(s), "l"(gmem_src));
}
__device__ __forceinline__ void cp_async_commit() {
    asm volatile("cp.async.commit_group;\n");
}
__device__ __forceinline__ void cp_async_wait0() {
    asm volatile("cp.async.wait_group 0;\n" ::: "memory");
}

template <int K, int MODE>
__global__ void __launch_bounds__(512, 1)
gemm_kernel(const float* __restrict__ A, const float* __restrict__ W,
            const float* __restrict__ dinv, const float* __restrict__ bias,
            float* __restrict__ C, int M) {
    constexpr int NT = K / BK;
    extern __shared__ float sm[];
    float* AsBase = sm;                       // 2 * BK * AS_STRIDE
    float* BsBase = sm + 2 * BK * AS_STRIDE;  // 2 * BK * DH

    const int tid = threadIdx.x;
    const int bm  = blockIdx.x * BM;
    const int tx  = tid & 31;    // 0..31 -> two col blocks of 4: tn, tn+128
    const int ty  = tid >> 5;    // 0..15 -> row block of 8
    const int tm  = ty * 8;
    const int tn  = tx * 4;

    // A-tile load: 128 rows x 16 cols = 512 float4; 1 per thread.
    const int arow  = tid >> 2;         // 0..127
    const int acol  = (tid & 3) * 4;    // 0,4,8,12
    const int garow = bm + arow;
    const bool aok  = (garow < M);
    const float* aptr = aok ? &A[(size_t)garow * K + acol] : nullptr;

    // B-tile load: 16 rows x 256 cols = 1024 float4; 2 per thread.
    const int brow0 = tid >> 6;               // 0..7
    const int bc0   = (tid & 63) * 4;         // 0..252
    const int brow1 = (tid + 512) >> 6;       // 8..15
    const float* wp0 = &W[(size_t)brow0 * DH + bc0];
    const float* wp1 = &W[(size_t)brow1 * DH + bc0];

    float acc[8][8];
#pragma unroll
    for (int i = 0; i < 8; i++)
#pragma unroll
        for (int j = 0; j < 8; j++) acc[i][j] = 0.0f;

    // prologue: tile 0
    {
        float4 av = make_float4(0.f, 0.f, 0.f, 0.f);
        if (aok) av = *reinterpret_cast<const float4*>(aptr);
        float* as = AsBase;
        as[(acol + 0) * AS_STRIDE + arow] = av.x;
        as[(acol + 1) * AS_STRIDE + arow] = av.y;
        as[(acol + 2) * AS_STRIDE + arow] = av.z;
        as[(acol + 3) * AS_STRIDE + arow] = av.w;
        cp_async16(&BsBase[brow0 * DH + bc0], wp0);
        cp_async16(&BsBase[brow1 * DH + bc0], wp1);
        cp_async_commit();
        cp_async_wait0();
        __syncthreads();
    }

    for (int t = 0; t < NT; t++) {
        const int curb = t & 1;
        const int nxtb = curb ^ 1;
        const bool has_next = (t + 1 < NT);
        float4 av;

        if (has_next) {
            const int k0 = (t + 1) * BK;
            av = make_float4(0.f, 0.f, 0.f, 0.f);
            if (aok) av = *reinterpret_cast<const float4*>(aptr + k0);
            cp_async16(&BsBase[nxtb * (BK * DH) + brow0 * DH + bc0], wp0 + (size_t)k0 * DH);
            cp_async16(&BsBase[nxtb * (BK * DH) + brow1 * DH + bc0], wp1 + (size_t)k0 * DH);
            cp_async_commit();
        }

        const float* as = AsBase + curb * (BK * AS_STRIDE);
        const float* bs = BsBase + curb * (BK * DH);
#pragma unroll
        for (int k = 0; k < BK; k++) {
            float a[8], b[8];
            *reinterpret_cast<float4*>(&a[0]) = *reinterpret_cast<const float4*>(&as[k * AS_STRIDE + tm]);
            *reinterpret_cast<float4*>(&a[4]) = *reinterpret_cast<const float4*>(&as[k * AS_STRIDE + tm + 4]);
            *reinterpret_cast<float4*>(&b[0]) = *reinterpret_cast<const float4*>(&bs[k * DH + tn]);
            *reinterpret_cast<float4*>(&b[4]) = *reinterpret_cast<const float4*>(&bs[k * DH + tn + 128]);
#pragma unroll
            for (int i = 0; i < 8; i++)
#pragma unroll
                for (int j = 0; j < 8; j++)
                    acc[i][j] = fmaf(a[i], b[j], acc[i][j]);
        }

        if (has_next) {
            float* asn = AsBase + nxtb * (BK * AS_STRIDE);
            asn[(acol + 0) * AS_STRIDE + arow] = av.x;
            asn[(acol + 1) * AS_STRIDE + arow] = av.y;
            asn[(acol + 2) * AS_STRIDE + arow] = av.z;
            asn[(acol + 3) * AS_STRIDE + arow] = av.w;
            cp_async_wait0();
            __syncthreads();
        }
    }

    // epilogue (two column blocks: tn and tn+128)
    float bb[8];
    *reinterpret_cast<float4*>(&bb[0]) = *reinterpret_cast<const float4*>(&bias[tn]);
    *reinterpret_cast<float4*>(&bb[4]) = *reinterpret_cast<const float4*>(&bias[tn + 128]);

#pragma unroll
    for (int i = 0; i < 8; i++) {
        int r = bm + tm + i;
        if (r < M) {
            float v[8];
#pragma unroll
            for (int j = 0; j < 8; j++) v[j] = fmaxf(acc[i][j] + bb[j], 0.0f);
            if (MODE == 0) {
                float s = dinv[r];
#pragma unroll
                for (int j = 0; j < 8; j++) v[j] *= s;
            }
            float* cp = &C[(size_t)r * DH];
            *reinterpret_cast<float4*>(cp + tn)       = *reinterpret_cast<float4*>(&v[0]);
            *reinterpret_cast<float4*>(cp + tn + 128) = *reinterpret_cast<float4*>(&v[4]);
        }
    }
}

// ---------------------------------------------------------------------------
// Gather layer 1 (128-dim raw features), unrolled x4:
//   z1[d] = dinv[d] * ( sum_{s in N(d)} dinv[s]*x[s]  +  dinv[d]*x[d] )
// ---------------------------------------------------------------------------
__global__ void __launch_bounds__(256)
gather_x_kernel(const float* __restrict__ x, const int* __restrict__ off,
                const int* __restrict__ sorted, const float* __restrict__ dinv,
                float* __restrict__ z, int n) {
    int warp = (blockIdx.x * blockDim.x + threadIdx.x) >> 5;
    int lane = threadIdx.x & 31;
    if (warp >= n) return;
    const int d  = warp;
    const int s0 = off[d];
    const int s1 = off[d + 1];
    const float dd = dinv[d];

    float4 a = __ldg(reinterpret_cast<const float4*>(x + (size_t)d * DIN) + lane);
    float4 v = make_float4(a.x * dd, a.y * dd, a.z * dd, a.w * dd);

    int j = s0;
    for (; j + 3 < s1; j += 4) {
        int sA = __ldg(&sorted[j]);
        int sB = __ldg(&sorted[j + 1]);
        int sC = __ldg(&sorted[j + 2]);
        int sD = __ldg(&sorted[j + 3]);
        float dA = __ldg(&dinv[sA]);
        float dB = __ldg(&dinv[sB]);
        float dC = __ldg(&dinv[sC]);
        float dD = __ldg(&dinv[sD]);
        float4 rA = __ldg(reinterpret_cast<const float4*>(x + (size_t)sA * DIN) + lane);
        float4 rB = __ldg(reinterpret_cast<const float4*>(x + (size_t)sB * DIN) + lane);
        float4 rC = __ldg(reinterpret_cast<const float4*>(x + (size_t)sC * DIN) + lane);
        float4 rD = __ldg(reinterpret_cast<const float4*>(x + (size_t)sD * DIN) + lane);
        v.x = fmaf(rA.x, dA, v.x); v.y = fmaf(rA.y, dA, v.y);
        v.z = fmaf(rA.z, dA, v.z); v.w = fmaf(rA.w, dA, v.w);
        v.x = fmaf(rB.x, dB, v.x); v.y = fmaf(rB.y, dB, v.y);
        v.z = fmaf(rB.z, dB, v.z); v.w = fmaf(rB.w, dB, v.w);
        v.x = fmaf(rC.x, dC, v.x); v.y = fmaf(rC.y, dC, v.y);
        v.z = fmaf(rC.z, dC, v.z); v.w = fmaf(rC.w, dC, v.w);
        v.x = fmaf(rD.x, dD, v.x); v.y = fmaf(rD.y, dD, v.y);
        v.z = fmaf(rD.z, dD, v.z); v.w = fmaf(rD.w, dD, v.w);
    }
    for (; j < s1; j++) {
        int s = __ldg(&sorted[j]);
        float ds = __ldg(&dinv[s]);
        float4 r = __ldg(reinterpret_cast<const float4*>(x + (size_t)s * DIN) + lane);
        v.x = fmaf(r.x, ds, v.x); v.y = fmaf(r.y, ds, v.y);
        v.z = fmaf(r.z, ds, v.z); v.w = fmaf(r.w, ds, v.w);
    }
    v.x *= dd; v.y *= dd; v.z *= dd; v.w *= dd;
    *(reinterpret_cast<float4*>(z + (size_t)d * DIN) + lane) = v;
}

// ---------------------------------------------------------------------------
// Gather layer 2 (256-dim, inputs pre-scaled by dinv[src]), unrolled x4:
//   z2[d] = dinv[d] * ( sum_{s in N(d)} hs[s]  +  hs[d] )
// ---------------------------------------------------------------------------
__global__ void __launch_bounds__(256)
gather_h_kernel(const float* __restrict__ hs, const int* __restrict__ off,
                const int* __restrict__ sorted, const float* __restrict__ dinv,
                float* __restrict__ z, int n) {
    int warp = (blockIdx.x * blockDim.x + threadIdx.x) >> 5;
    int lane = threadIdx.x & 31;
    if (warp >= n) return;
    const int d  = warp;
    const int s0 = off[d];
    const int s1 = off[d + 1];

    const float4* self = reinterpret_cast<const float4*>(hs + (size_t)d * DH) + lane;
    float4 v0 = __ldg(self);
    float4 v1 = __ldg(self + 32);

    int j = s0;
    for (; j + 3 < s1; j += 4) {
        int sA = __ldg(&sorted[j]);
        int sB = __ldg(&sorted[j + 1]);
        int sC = __ldg(&sorted[j + 2]);
        int sD = __ldg(&sorted[j + 3]);
        const float4* inA = reinterpret_cast<const float4*>(hs + (size_t)sA * DH) + lane;
        const float4* inB = reinterpret_cast<const float4*>(hs + (size_t)sB * DH) + lane;
        const float4* inC = reinterpret_cast<const float4*>(hs + (size_t)sC * DH) + lane;
        const float4* inD = reinterpret_cast<const float4*>(hs + (size_t)sD * DH) + lane;
        float4 a0 = __ldg(inA), a1 = __ldg(inA + 32);
        float4 b0 = __ldg(inB), b1 = __ldg(inB + 32);
        float4 c0 = __ldg(inC), c1 = __ldg(inC + 32);
        float4 e0 = __ldg(inD), e1 = __ldg(inD + 32);
        v0.x += (a0.x + b0.x) + (c0.x + e0.x);
        v0.y += (a0.y + b0.y) + (c0.y + e0.y);
        v0.z += (a0.z + b0.z) + (c0.z + e0.z);
        v0.w += (a0.w + b0.w) + (c0.w + e0.w);
        v1.x += (a1.x + b1.x) + (c1.x + e1.x);
        v1.y += (a1.y + b1.y) + (c1.y + e1.y);
        v1.z += (a1.z + b1.z) + (c1.z + e1.z);
        v1.w += (a1.w + b1.w) + (c1.w + e1.w);
    }
    for (; j < s1; j++) {
        int s = __ldg(&sorted[j]);
        const float4* in = reinterpret_cast<const float4*>(hs + (size_t)s * DH) + lane;
        float4 a0 = __ldg(in);
        float4 a1 = __ldg(in + 32);
        v0.x += a0.x; v0.y += a0.y; v0.z += a0.z; v0.w += a0.w;
        v1.x += a1.x; v1.y += a1.y; v1.z += a1.z; v1.w += a1.w;
    }

    const float dd = dinv[d];
    v0.x *= dd; v0.y *= dd; v0.z *= dd; v0.w *= dd;
    v1.x *= dd; v1.y *= dd; v1.z *= dd; v1.w *= dd;

    float4* op = reinterpret_cast<float4*>(z + (size_t)d * DH) + lane;
    op[0]  = v0;
    op[32] = v1;
}

// ---------------------------------------------------------------------------
// Launch
// ---------------------------------------------------------------------------
extern "C" void kernel_launch(void* const* d_in, const int* in_sizes, int n_in,
                              void* d_out, int out_size) {
    const float* x  = (const float*)d_in[0];
    const int*   ei = (const int*)d_in[1];
    const float* W1 = (const float*)d_in[2];
    const float* b1 = (const float*)d_in[3];
    const float* W2 = (const float*)d_in[4];
    const float* b2 = (const float*)d_in[5];
    float* out = (float*)d_out;

    const int n = in_sizes[0] / DIN;
    const int e = in_sizes[1] / 2;
    const int* esrc = ei;
    const int* edst = ei + e;

    float *dinv, *buf1, *buf2;
    int *cnt, *off, *cur, *srt;
    cudaGetSymbolAddress((void**)&dinv, g_dinv);
    cudaGetSymbolAddress((void**)&buf1, g_buf1);
    cudaGetSymbolAddress((void**)&buf2, g_buf2);
    cudaGetSymbolAddress((void**)&cnt,  g_cnt);
    cudaGetSymbolAddress((void**)&off,  g_off);
    cudaGetSymbolAddress((void**)&cur,  g_cur);
    cudaGetSymbolAddress((void**)&srt,  g_src);

    static bool attr_done = false;
    if (!attr_done) {
        cudaFuncSetAttribute(gemm_kernel<DIN, 0>, cudaFuncAttributeMaxDynamicSharedMemorySize, GEMM_SMEM);
        cudaFuncSetAttribute(gemm_kernel<DH, 1>,  cudaFuncAttributeMaxDynamicSharedMemorySize, GEMM_SMEM);
        attr_done = true;
    }

    const int T = 256;
    const int e_blk = (e + T - 1) / T;
    const int g_blk = (n + (T / 32) - 1) / (T / 32);
    const int gemm_blk = (n + BM - 1) / BM;

    // ----- CSR build -----
    cudaMemsetAsync(cnt, 0, (size_t)n * sizeof(int));
    count_kernel<<<e_blk, T>>>(edst, e, cnt);
    scan_kernel<<<1, 1024>>>(cnt, off, cur, dinv, n);
    fill_kernel<<<e_blk, T>>>(esrc, edst, e, cur, srt);

    // ----- Layer 1 (aggregate-first: 128-dim gather) -----
    gather_x_kernel<<<g_blk, T>>>(x, off, srt, dinv, buf1, n);
    gemm_kernel<DIN, 0><<<gemm_blk, 512, GEMM_SMEM>>>(buf1, W1, dinv, b1, buf2, n);

    // ----- Layer 2 (aggregate-then-transform) -----
    gather_h_kernel<<<g_blk, T>>>(buf2, off, srt, dinv, buf1, n);
    gemm_kernel<DH, 1><<<gemm_blk, 512, GEMM_SMEM>>>(buf1, W2, dinv, b2, out, n);
}

// round 9
// speedup vs baseline: 1.2289x; 1.1252x over previous
#include <cuda_runtime.h>
#include <cstdint>

#define MAXN  100000
#define MAXE  2000000
#define DH    256
#define DIN   128

// Scratch (static device globals — no allocation allowed)
__device__ float g_dinv[MAXN];
__device__ float g_buf1[(size_t)MAXN * DH];
__device__ float g_buf2[(size_t)MAXN * DH];
__device__ int   g_cnt[MAXN];
__device__ int   g_off[MAXN + 1];
__device__ int   g_cur[MAXN];
__device__ int   g_src[MAXE];

// ---------------------------------------------------------------------------
// CSR build
// ---------------------------------------------------------------------------
__global__ void count_kernel(const int* __restrict__ edst, int e, int* __restrict__ cnt) {
    int i = blockIdx.x * blockDim.x + threadIdx.x;
    if (i < e) atomicAdd(&cnt[edst[i]], 1);
}

__global__ void __launch_bounds__(1024)
scan_kernel(const int* __restrict__ cnt, int* __restrict__ off, int* __restrict__ cur,
            float* __restrict__ dinv, int n) {
    __shared__ int ssum[1024];
    const int tid = threadIdx.x;
    const int chunk = (n + 1023) >> 10;
    const int begin = tid * chunk;
    const int end   = min(begin + chunk, n);

    int mysum = 0;
    for (int i = begin; i < end; i++) mysum += cnt[i];
    ssum[tid] = mysum;
    __syncthreads();
    for (int d = 1; d < 1024; d <<= 1) {
        int add = (tid >= d) ? ssum[tid - d] : 0;
        __syncthreads();
        ssum[tid] += add;
        __syncthreads();
    }
    int run = ssum[tid] - mysum;
    for (int i = begin; i < end; i++) {
        int c = cnt[i];
        off[i] = run;
        cur[i] = run;
        dinv[i] = rsqrtf(1.0f + (float)c);
        run += c;
    }
    if (tid == 1023) off[n] = ssum[1023];
}

__global__ void fill_kernel(const int* __restrict__ esrc, const int* __restrict__ edst,
                            int e, int* __restrict__ cur, int* __restrict__ sorted) {
    int i = blockIdx.x * blockDim.x + threadIdx.x;
    if (i < e) {
        int d = edst[i];
        int pos = atomicAdd(&cur[d], 1);
        sorted[pos] = esrc[i];
    }
}

// ---------------------------------------------------------------------------
// SGEMM, BM=64 x BN=256(full), BK=16, 256 threads, 8x8/thread, double-buffered.
//   MODE 0: C = dinv[m] * relu(acc + b)
//   MODE 1: C = relu(acc + b)
// 32K regs + 41.5KB smem per CTA -> 2 CTAs/SM (sync/epilogue overlap).
// Columns split {tn, tn+128}, tn = tx*4: conflict-free B-fragment LDS.
// ---------------------------------------------------------------------------
#define BM 64
#define BK 16
#define AS_STRIDE 68   // 64 + 4 pad, 16B-aligned

__device__ __forceinline__ void cp_async16(void* smem_dst, const void* gmem_src) {
    uint32_t s = (uint32_t)__cvta_generic_to_shared(smem_dst);
    asm volatile("cp.async.cg.shared.global [%0], [%1], 16;\n" :: "r"(s), "l"(gmem_src));
}
__device__ __forceinline__ void cp_async_commit() {
    asm volatile("cp.async.commit_group;\n");
}
__device__ __forceinline__ void cp_async_wait0() {
    asm volatile("cp.async.wait_group 0;\n" ::: "memory");
}

template <int K, int MODE>
__global__ void __launch_bounds__(256, 2)
gemm_kernel(const float* __restrict__ A, const float* __restrict__ W,
            const float* __restrict__ dinv, const float* __restrict__ bias,
            float* __restrict__ C, int M) {
    constexpr int NT = K / BK;
    __shared__ float As[2][BK * AS_STRIDE];
    __shared__ float Bs[2][BK * DH];

    const int tid = threadIdx.x;
    const int bm  = blockIdx.x * BM;
    const int tx  = tid & 31;    // col blocks {tx*4, tx*4+128}
    const int ty  = tid >> 5;    // 0..7 -> row block of 8
    const int tm  = ty * 8;
    const int tn  = tx * 4;

    // A-tile: 64 rows x 16 cols = 256 float4; 1 per thread.
    const int arow  = tid >> 2;         // 0..63
    const int acol  = (tid & 3) * 4;    // 0,4,8,12
    const int garow = bm + arow;
    const bool aok  = (garow < M);
    const float* aptr = aok ? &A[(size_t)garow * K + acol] : nullptr;

    // B-tile: 16 rows x 256 cols = 1024 float4; 4 per thread.
    const int bcol = (tid & 63) * 4;    // 0..252
    const int br0  = tid >> 6;          // 0..3
    const float* wp[4];
#pragma unroll
    for (int r = 0; r < 4; r++) wp[r] = &W[(size_t)(br0 + r * 4) * DH + bcol];

    float acc[8][8];
#pragma unroll
    for (int i = 0; i < 8; i++)
#pragma unroll
        for (int j = 0; j < 8; j++) acc[i][j] = 0.0f;

    // prologue: tile 0
    {
        float4 av = make_float4(0.f, 0.f, 0.f, 0.f);
        if (aok) av = *reinterpret_cast<const float4*>(aptr);
        float* as = &As[0][0];
        as[(acol + 0) * AS_STRIDE + arow] = av.x;
        as[(acol + 1) * AS_STRIDE + arow] = av.y;
        as[(acol + 2) * AS_STRIDE + arow] = av.z;
        as[(acol + 3) * AS_STRIDE + arow] = av.w;
#pragma unroll
        for (int r = 0; r < 4; r++)
            cp_async16(&Bs[0][(br0 + r * 4) * DH + bcol], wp[r]);
        cp_async_commit();
        cp_async_wait0();
        __syncthreads();
    }

    for (int t = 0; t < NT; t++) {
        const int curb = t & 1;
        const int nxtb = curb ^ 1;
        const bool has_next = (t + 1 < NT);
        float4 av;

        if (has_next) {
            const int k0 = (t + 1) * BK;
            av = make_float4(0.f, 0.f, 0.f, 0.f);
            if (aok) av = *reinterpret_cast<const float4*>(aptr + k0);
#pragma unroll
            for (int r = 0; r < 4; r++)
                cp_async16(&Bs[nxtb][(br0 + r * 4) * DH + bcol], wp[r] + (size_t)k0 * DH);
            cp_async_commit();
        }

        const float* as = &As[curb][0];
        const float* bs = &Bs[curb][0];
#pragma unroll
        for (int k = 0; k < BK; k++) {
            float a[8], b[8];
            *reinterpret_cast<float4*>(&a[0]) = *reinterpret_cast<const float4*>(&as[k * AS_STRIDE + tm]);
            *reinterpret_cast<float4*>(&a[4]) = *reinterpret_cast<const float4*>(&as[k * AS_STRIDE + tm + 4]);
            *reinterpret_cast<float4*>(&b[0]) = *reinterpret_cast<const float4*>(&bs[k * DH + tn]);
            *reinterpret_cast<float4*>(&b[4]) = *reinterpret_cast<const float4*>(&bs[k * DH + tn + 128]);
#pragma unroll
            for (int i = 0; i < 8; i++)
#pragma unroll
                for (int j = 0; j < 8; j++)
                    acc[i][j] = fmaf(a[i], b[j], acc[i][j]);
        }

        if (has_next) {
            float* asn = &As[nxtb][0];
            asn[(acol + 0) * AS_STRIDE + arow] = av.x;
            asn[(acol + 1) * AS_STRIDE + arow] = av.y;
            asn[(acol + 2) * AS_STRIDE + arow] = av.z;
            asn[(acol + 3) * AS_STRIDE + arow] = av.w;
            cp_async_wait0();
            __syncthreads();
        }
    }

    // epilogue (two column blocks: tn and tn+128)
    float bb[8];
    *reinterpret_cast<float4*>(&bb[0]) = *reinterpret_cast<const float4*>(&bias[tn]);
    *reinterpret_cast<float4*>(&bb[4]) = *reinterpret_cast<const float4*>(&bias[tn + 128]);

#pragma unroll
    for (int i = 0; i < 8; i++) {
        int r = bm + tm + i;
        if (r < M) {
            float v[8];
#pragma unroll
            for (int j = 0; j < 8; j++) v[j] = fmaxf(acc[i][j] + bb[j], 0.0f);
            if (MODE == 0) {
                float s = dinv[r];
#pragma unroll
                for (int j = 0; j < 8; j++) v[j] *= s;
            }
            float* cp = &C[(size_t)r * DH];
            *reinterpret_cast<float4*>(cp + tn)       = *reinterpret_cast<float4*>(&v[0]);
            *reinterpret_cast<float4*>(cp + tn + 128) = *reinterpret_cast<float4*>(&v[4]);
        }
    }
}

// ---------------------------------------------------------------------------
// Gather layer 1 (128-dim raw features), unrolled x4:
//   z1[d] = dinv[d] * ( sum_{s in N(d)} dinv[s]*x[s]  +  dinv[d]*x[d] )
// ---------------------------------------------------------------------------
__global__ void __launch_bounds__(256)
gather_x_kernel(const float* __restrict__ x, const int* __restrict__ off,
                const int* __restrict__ sorted, const float* __restrict__ dinv,
                float* __restrict__ z, int n) {
    int warp = (blockIdx.x * blockDim.x + threadIdx.x) >> 5;
    int lane = threadIdx.x & 31;
    if (warp >= n) return;
    const int d  = warp;
    const int s0 = off[d];
    const int s1 = off[d + 1];
    const float dd = dinv[d];

    float4 a = __ldg(reinterpret_cast<const float4*>(x + (size_t)d * DIN) + lane);
    float4 v = make_float4(a.x * dd, a.y * dd, a.z * dd, a.w * dd);

    int j = s0;
    for (; j + 3 < s1; j += 4) {
        int sA = __ldg(&sorted[j]);
        int sB = __ldg(&sorted[j + 1]);
        int sC = __ldg(&sorted[j + 2]);
        int sD = __ldg(&sorted[j + 3]);
        float dA = __ldg(&dinv[sA]);
        float dB = __ldg(&dinv[sB]);
        float dC = __ldg(&dinv[sC]);
        float dD = __ldg(&dinv[sD]);
        float4 rA = __ldg(reinterpret_cast<const float4*>(x + (size_t)sA * DIN) + lane);
        float4 rB = __ldg(reinterpret_cast<const float4*>(x + (size_t)sB * DIN) + lane);
        float4 rC = __ldg(reinterpret_cast<const float4*>(x + (size_t)sC * DIN) + lane);
        float4 rD = __ldg(reinterpret_cast<const float4*>(x + (size_t)sD * DIN) + lane);
        v.x = fmaf(rA.x, dA, v.x); v.y = fmaf(rA.y, dA, v.y);
        v.z = fmaf(rA.z, dA, v.z); v.w = fmaf(rA.w, dA, v.w);
        v.x = fmaf(rB.x, dB, v.x); v.y = fmaf(rB.y, dB, v.y);
        v.z = fmaf(rB.z, dB, v.z); v.w = fmaf(rB.w, dB, v.w);
        v.x = fmaf(rC.x, dC, v.x); v.y = fmaf(rC.y, dC, v.y);
        v.z = fmaf(rC.z, dC, v.z); v.w = fmaf(rC.w, dC, v.w);
        v.x = fmaf(rD.x, dD, v.x); v.y = fmaf(rD.y, dD, v.y);
        v.z = fmaf(rD.z, dD, v.z); v.w = fmaf(rD.w, dD, v.w);
    }
    for (; j < s1; j++) {
        int s = __ldg(&sorted[j]);
        float ds = __ldg(&dinv[s]);
        float4 r = __ldg(reinterpret_cast<const float4*>(x + (size_t)s * DIN) + lane);
        v.x = fmaf(r.x, ds, v.x); v.y = fmaf(r.y, ds, v.y);
        v.z = fmaf(r.z, ds, v.z); v.w = fmaf(r.w, ds, v.w);
    }
    v.x *= dd; v.y *= dd; v.z *= dd; v.w *= dd;
    *(reinterpret_cast<float4*>(z + (size_t)d * DIN) + lane) = v;
}

// ---------------------------------------------------------------------------
// Gather layer 2 (256-dim, pre-scaled inputs), TWO warps per node:
//   warp half h (0/1) owns float4s [h*32 + lane] of the 64-float4 row.
//   z2[d] = dinv[d] * ( sum_{s in N(d)} hs[s]  +  hs[d] )
// ---------------------------------------------------------------------------
__global__ void __launch_bounds__(256)
gather_h_kernel(const float* __restrict__ hs, const int* __restrict__ off,
                const int* __restrict__ sorted, const float* __restrict__ dinv,
                float* __restrict__ z, int n) {
    int gwarp = (blockIdx.x * blockDim.x + threadIdx.x) >> 5;
    int lane  = threadIdx.x & 31;
    int d     = gwarp >> 1;
    if (d >= n) return;
    const int foff = ((gwarp & 1) << 5) + lane;  // float4 index within 64-float4 row
    const int s0 = off[d];
    const int s1 = off[d + 1];

    const float4* base = reinterpret_cast<const float4*>(hs);
    float4 v = __ldg(base + (size_t)d * 64 + foff);

    int j = s0;
    for (; j + 3 < s1; j += 4) {
        int sA = __ldg(&sorted[j]);
        int sB = __ldg(&sorted[j + 1]);
        int sC = __ldg(&sorted[j + 2]);
        int sD = __ldg(&sorted[j + 3]);
        float4 a = __ldg(base + (size_t)sA * 64 + foff);
        float4 b = __ldg(base + (size_t)sB * 64 + foff);
        float4 c = __ldg(base + (size_t)sC * 64 + foff);
        float4 e = __ldg(base + (size_t)sD * 64 + foff);
        v.x += (a.x + b.x) + (c.x + e.x);
        v.y += (a.y + b.y) + (c.y + e.y);
        v.z += (a.z + b.z) + (c.z + e.z);
        v.w += (a.w + b.w) + (c.w + e.w);
    }
    for (; j < s1; j++) {
        int s = __ldg(&sorted[j]);
        float4 a = __ldg(base + (size_t)s * 64 + foff);
        v.x += a.x; v.y += a.y; v.z += a.z; v.w += a.w;
    }

    const float dd = dinv[d];
    v.x *= dd; v.y *= dd; v.z *= dd; v.w *= dd;
    reinterpret_cast<float4*>(z)[(size_t)d * 64 + foff] = v;
}

// ---------------------------------------------------------------------------
// Launch
// ---------------------------------------------------------------------------
extern "C" void kernel_launch(void* const* d_in, const int* in_sizes, int n_in,
                              void* d_out, int out_size) {
    const float* x  = (const float*)d_in[0];
    const int*   ei = (const int*)d_in[1];
    const float* W1 = (const float*)d_in[2];
    const float* b1 = (const float*)d_in[3];
    const float* W2 = (const float*)d_in[4];
    const float* b2 = (const float*)d_in[5];
    float* out = (float*)d_out;

    const int n = in_sizes[0] / DIN;
    const int e = in_sizes[1] / 2;
    const int* esrc = ei;
    const int* edst = ei + e;

    float *dinv, *buf1, *buf2;
    int *cnt, *off, *cur, *srt;
    cudaGetSymbolAddress((void**)&dinv, g_dinv);
    cudaGetSymbolAddress((void**)&buf1, g_buf1);
    cudaGetSymbolAddress((void**)&buf2, g_buf2);
    cudaGetSymbolAddress((void**)&cnt,  g_cnt);
    cudaGetSymbolAddress((void**)&off,  g_off);
    cudaGetSymbolAddress((void**)&cur,  g_cur);
    cudaGetSymbolAddress((void**)&srt,  g_src);

    const int T = 256;
    const int e_blk  = (e + T - 1) / T;
    const int gx_blk = (n + (T / 32) - 1) / (T / 32);       // 1 warp / node
    const int gh_blk = (2 * n + (T / 32) - 1) / (T / 32);   // 2 warps / node
    const int gemm_blk = (n + BM - 1) / BM;

    // ----- CSR build -----
    cudaMemsetAsync(cnt, 0, (size_t)n * sizeof(int));
    count_kernel<<<e_blk, T>>>(edst, e, cnt);
    scan_kernel<<<1, 1024>>>(cnt, off, cur, dinv, n);
    fill_kernel<<<e_blk, T>>>(esrc, edst, e, cur, srt);

    // ----- Layer 1 (aggregate-first: 128-dim gather) -----
    gather_x_kernel<<<gx_blk, T>>>(x, off, srt, dinv, buf1, n);
    gemm_kernel<DIN, 0><<<gemm_blk, T>>>(buf1, W1, dinv, b1, buf2, n);

    // ----- Layer 2 (aggregate-then-transform) -----
    gather_h_kernel<<<gh_blk, T>>>(buf2, off, srt, dinv, buf1, n);
    gemm_kernel<DH, 1><<<gemm_blk, T>>>(buf1, W2, dinv, b2, out, n);
}

// round 12
// speedup vs baseline: 1.2366x; 1.0063x over previous
#include <cuda_runtime.h>
#include <cstdint>

#define MAXN  100000
#define MAXE  2000000
#define DH    256
#define DIN   128

// Scratch (static device globals — no allocation allowed)
__device__ float g_dinv[MAXN];
__device__ float g_buf1[(size_t)MAXN * DH];
__device__ float g_buf2[(size_t)MAXN * DH];
__device__ int   g_cnt[MAXN];
__device__ int   g_off[MAXN + 1];
__device__ int   g_cur[MAXN];
__device__ int   g_src[MAXE];

// ---------------------------------------------------------------------------
// CSR build
// ---------------------------------------------------------------------------
__global__ void count_kernel(const int* __restrict__ edst, int e, int* __restrict__ cnt) {
    int i = blockIdx.x * blockDim.x + threadIdx.x;
    if (i < e) atomicAdd(&cnt[edst[i]], 1);
}

__global__ void __launch_bounds__(1024)
scan_kernel(const int* __restrict__ cnt, int* __restrict__ off, int* __restrict__ cur,
            float* __restrict__ dinv, int n) {
    __shared__ int ssum[1024];
    const int tid = threadIdx.x;
    const int chunk = (n + 1023) >> 10;
    const int begin = tid * chunk;
    const int end   = min(begin + chunk, n);

    int mysum = 0;
    for (int i = begin; i < end; i++) mysum += cnt[i];
    ssum[tid] = mysum;
    __syncthreads();
    for (int d = 1; d < 1024; d <<= 1) {
        int add = (tid >= d) ? ssum[tid - d] : 0;
        __syncthreads();
        ssum[tid] += add;
        __syncthreads();
    }
    int run = ssum[tid] - mysum;
    for (int i = begin; i < end; i++) {
        int c = cnt[i];
        off[i] = run;
        cur[i] = run;
        dinv[i] = rsqrtf(1.0f + (float)c);
        run += c;
    }
    if (tid == 1023) off[n] = ssum[1023];
}

__global__ void fill_kernel(const int* __restrict__ esrc, const int* __restrict__ edst,
                            int e, int* __restrict__ cur, int* __restrict__ sorted) {
    int i = blockIdx.x * blockDim.x + threadIdx.x;
    if (i < e) {
        int d = edst[i];
        int pos = atomicAdd(&cur[d], 1);
        sorted[pos] = esrc[i];
    }
}

// ---------------------------------------------------------------------------
// Tensor-core SGEMM via mma.sync m16n8k8 tf32, 3xTF32 split (fp32-grade).
//   MODE 0: C = dinv[m] * relu(acc + b)
//   MODE 1: C = relu(acc + b)
// BM=64, BN=256(full), BK=32, 256 threads (8 warps as 2x4; warp = 32x64).
// Double-buffered dynamic smem; B via cp.async; 2 CTAs/SM.
// ---------------------------------------------------------------------------
#define BM     64
#define AS_STR 36     // 32 + 4 pad: A-frag LDS conflict-free
#define BS_STR 260    // 256 + 4 pad: B-frag LDS conflict-free
#define A_BUF  (64 * AS_STR)
#define B_BUF  (32 * BS_STR)
#define GEMM_SMEM ((2 * A_BUF + 2 * B_BUF) * 4)

__device__ __forceinline__ void cp_async16(void* smem_dst, const void* gmem_src) {
    uint32_t s = (uint32_t)__cvta_generic_to_shared(smem_dst);
    asm volatile("cp.async.cg.shared.global [%0], [%1], 16;\n" :: "r"(s), "l"(gmem_src));
}
__device__ __forceinline__ void cp_async_commit() {
    asm volatile("cp.async.commit_group;\n");
}
__device__ __forceinline__ void cp_async_wait0() {
    asm volatile("cp.async.wait_group 0;\n" ::: "memory");
}

// split x -> tf32 hi + tf32 lo (hi = rna(x), lo = rna(x - hi))
__device__ __forceinline__ void split_tf32(float x, uint32_t& hi, uint32_t& lo) {
    asm("cvt.rna.tf32.f32 %0, %1;" : "=r"(hi) : "f"(x));
    float lof = x - __uint_as_float(hi);
    asm("cvt.rna.tf32.f32 %0, %1;" : "=r"(lo) : "f"(lof));
}

__device__ __forceinline__ void mma_tf32(float* c, const uint32_t* a, const uint32_t* b) {
    asm volatile(
        "mma.sync.aligned.m16n8k8.row.col.f32.tf32.tf32.f32 "
        "{%0,%1,%2,%3}, {%4,%5,%6,%7}, {%8,%9}, {%0,%1,%2,%3};"
        : "+f"(c[0]), "+f"(c[1]), "+f"(c[2]), "+f"(c[3])
        : "r"(a[0]), "r"(a[1]), "r"(a[2]), "r"(a[3]), "r"(b[0]), "r"(b[1]));
}

template <int K, int MODE>
__global__ void __launch_bounds__(256, 2)
gemm_mma_kernel(const float* __restrict__ A, const float* __restrict__ W,
                const float* __restrict__ dinv, const float* __restrict__ bias,
                float* __restrict__ C, int M) {
    constexpr int NT = K / 32;
    extern __shared__ float sm[];
    float* AsB = sm;               // [2][64][AS_STR]
    float* BsB = sm + 2 * A_BUF;   // [2][32][BS_STR]

    const int tid  = threadIdx.x;
    const int bm   = blockIdx.x * BM;
    const int wid  = tid >> 5;
    const int lane = tid & 31;
    const int wm   = wid >> 2;     // 0..1 (row half)
    const int wn   = wid & 3;      // 0..3 (col quarter)
    const int g    = lane >> 2;    // group 0..7
    const int t    = lane & 3;     // thread-in-group 0..3

    // A global-load mapping: 64x32 floats = 512 float4; 2/thread (i, i+256)
    const int ar0 = tid >> 3;           // 0..31
    const int ac0 = (tid & 7) * 4;      // 0..28
    const bool aok0 = (bm + ar0)      < M;
    const bool aok1 = (bm + ar0 + 32) < M;
    const float* aP0 = &A[(size_t)(bm + ar0)      * K + ac0];
    const float* aP1 = &A[(size_t)(bm + ar0 + 32) * K + ac0];

    // B cp.async mapping: 32x256 floats = 2048 float4; 8/thread
    const int bk0 = tid >> 6;           // 0..3 (+ r*4)
    const int bn0 = (tid & 63) * 4;     // 0..252

    float acc[2][8][4];
#pragma unroll
    for (int i = 0; i < 2; i++)
#pragma unroll
        for (int j = 0; j < 8; j++)
#pragma unroll
            for (int q = 0; q < 4; q++) acc[i][j][q] = 0.0f;

    // ---- prologue: tile 0 ----
    {
        float4 v0 = make_float4(0.f, 0.f, 0.f, 0.f);
        float4 v1 = make_float4(0.f, 0.f, 0.f, 0.f);
        if (aok0) v0 = *reinterpret_cast<const float4*>(aP0);
        if (aok1) v1 = *reinterpret_cast<const float4*>(aP1);
        *reinterpret_cast<float4*>(&AsB[ar0 * AS_STR + ac0])        = v0;
        *reinterpret_cast<float4*>(&AsB[(ar0 + 32) * AS_STR + ac0]) = v1;
#pragma unroll
        for (int r = 0; r < 8; r++) {
            int k = bk0 + r * 4;
            cp_async16(&BsB[k * BS_STR + bn0], &W[(size_t)k * DH + bn0]);
        }
        cp_async_commit();
        cp_async_wait0();
        __syncthreads();
    }

    for (int tt = 0; tt < NT; tt++) {
        const int curb = tt & 1;
        const int nxtb = curb ^ 1;
        const bool has_next = (tt + 1 < NT);
        float4 v0, v1;

        if (has_next) {
            const int k0 = (tt + 1) * 32;
            v0 = make_float4(0.f, 0.f, 0.f, 0.f);
            v1 = make_float4(0.f, 0.f, 0.f, 0.f);
            if (aok0) v0 = *reinterpret_cast<const float4*>(aP0 + k0);
            if (aok1) v1 = *reinterpret_cast<const float4*>(aP1 + k0);
#pragma unroll
            for (int r = 0; r < 8; r++) {
                int k = bk0 + r * 4;
                cp_async16(&BsB[nxtb * B_BUF + k * BS_STR + bn0],
                           &W[(size_t)(k0 + k) * DH + bn0]);
            }
            cp_async_commit();
        }

        const float* as = AsB + curb * A_BUF;
        const float* bs = BsB + curb * B_BUF;

#pragma unroll
        for (int ks = 0; ks < 4; ks++) {
            const int kb = ks * 8;
            // A fragments for both m-tiles (m16n8k8 A layout)
            uint32_t aH[2][4], aL[2][4];
#pragma unroll
            for (int mt = 0; mt < 2; mt++) {
                const int rb = wm * 32 + mt * 16;
                float x0 = as[(rb + g)     * AS_STR + kb + t];
                float x1 = as[(rb + g + 8) * AS_STR + kb + t];
                float x2 = as[(rb + g)     * AS_STR + kb + t + 4];
                float x3 = as[(rb + g + 8) * AS_STR + kb + t + 4];
                split_tf32(x0, aH[mt][0], aL[mt][0]);
                split_tf32(x1, aH[mt][1], aL[mt][1]);
                split_tf32(x2, aH[mt][2], aL[mt][2]);
                split_tf32(x3, aH[mt][3], aL[mt][3]);
            }
#pragma unroll
            for (int nh = 0; nh < 2; nh++) {
                uint32_t bH[4][2], bL[4][2];
#pragma unroll
                for (int nt = 0; nt < 4; nt++) {
                    const int nb = wn * 64 + (nh * 4 + nt) * 8 + g;
                    float y0 = bs[(kb + t)     * BS_STR + nb];
                    float y1 = bs[(kb + t + 4) * BS_STR + nb];
                    split_tf32(y0, bH[nt][0], bL[nt][0]);
                    split_tf32(y1, bH[nt][1], bL[nt][1]);
                }
#pragma unroll
                for (int mt = 0; mt < 2; mt++)
#pragma unroll
                    for (int nt = 0; nt < 4; nt++) {
                        float* c = acc[mt][nh * 4 + nt];
                        mma_tf32(c, aH[mt], bL[nt]);   // cross terms first
                        mma_tf32(c, aL[mt], bH[nt]);
                        mma_tf32(c, aH[mt], bH[nt]);   // main term
                    }
            }
        }

        if (has_next) {
            float* asn = AsB + nxtb * A_BUF;
            *reinterpret_cast<float4*>(&asn[ar0 * AS_STR + ac0])        = v0;
            *reinterpret_cast<float4*>(&asn[(ar0 + 32) * AS_STR + ac0]) = v1;
            cp_async_wait0();
            __syncthreads();
        }
    }

    // ---- epilogue ----
#pragma unroll
    for (int mt = 0; mt < 2; mt++) {
        const int r0 = bm + wm * 32 + mt * 16 + g;
        const int r1 = r0 + 8;
        float s0 = 1.0f, s1 = 1.0f;
        if (MODE == 0) {
            if (r0 < M) s0 = dinv[r0];
            if (r1 < M) s1 = dinv[r1];
        }
#pragma unroll
        for (int nt = 0; nt < 8; nt++) {
            const int c0 = wn * 64 + nt * 8 + 2 * t;
            const float bb0 = bias[c0];
            const float bb1 = bias[c0 + 1];
            float v00 = fmaxf(acc[mt][nt][0] + bb0, 0.0f) * s0;
            float v01 = fmaxf(acc[mt][nt][1] + bb1, 0.0f) * s0;
            float v10 = fmaxf(acc[mt][nt][2] + bb0, 0.0f) * s1;
            float v11 = fmaxf(acc[mt][nt][3] + bb1, 0.0f) * s1;
            if (r0 < M)
                *reinterpret_cast<float2*>(&C[(size_t)r0 * DH + c0]) = make_float2(v00, v01);
            if (r1 < M)
                *reinterpret_cast<float2*>(&C[(size_t)r1 * DH + c0]) = make_float2(v10, v11);
        }
    }
}

// ---------------------------------------------------------------------------
// Gather layer 1 (128-dim raw features), unrolled x4:
//   z1[d] = dinv[d] * ( sum_{s in N(d)} dinv[s]*x[s]  +  dinv[d]*x[d] )
// ---------------------------------------------------------------------------
__global__ void __launch_bounds__(256)
gather_x_kernel(const float* __restrict__ x, const int* __restrict__ off,
                const int* __restrict__ sorted, const float* __restrict__ dinv,
                float* __restrict__ z, int n) {
    int warp = (blockIdx.x * blockDim.x + threadIdx.x) >> 5;
    int lane = threadIdx.x & 31;
    if (warp >= n) return;
    const int d  = warp;
    const int s0 = off[d];
    const int s1 = off[d + 1];
    const float dd = dinv[d];

    float4 a = __ldg(reinterpret_cast<const float4*>(x + (size_t)d * DIN) + lane);
    float4 v = make_float4(a.x * dd, a.y * dd, a.z * dd, a.w * dd);

    int j = s0;
    for (; j + 3 < s1; j += 4) {
        int sA = __ldg(&sorted[j]);
        int sB = __ldg(&sorted[j + 1]);
        int sC = __ldg(&sorted[j + 2]);
        int sD = __ldg(&sorted[j + 3]);
        float dA = __ldg(&dinv[sA]);
        float dB = __ldg(&dinv[sB]);
        float dC = __ldg(&dinv[sC]);
        float dD = __ldg(&dinv[sD]);
        float4 rA = __ldg(reinterpret_cast<const float4*>(x + (size_t)sA * DIN) + lane);
        float4 rB = __ldg(reinterpret_cast<const float4*>(x + (size_t)sB * DIN) + lane);
        float4 rC = __ldg(reinterpret_cast<const float4*>(x + (size_t)sC * DIN) + lane);
        float4 rD = __ldg(reinterpret_cast<const float4*>(x + (size_t)sD * DIN) + lane);
        v.x = fmaf(rA.x, dA, v.x); v.y = fmaf(rA.y, dA, v.y);
        v.z = fmaf(rA.z, dA, v.z); v.w = fmaf(rA.w, dA, v.w);
        v.x = fmaf(rB.x, dB, v.x); v.y = fmaf(rB.y, dB, v.y);
        v.z = fmaf(rB.z, dB, v.z); v.w = fmaf(rB.w, dB, v.w);
        v.x = fmaf(rC.x, dC, v.x); v.y = fmaf(rC.y, dC, v.y);
        v.z = fmaf(rC.z, dC, v.z); v.w = fmaf(rC.w, dC, v.w);
        v.x = fmaf(rD.x, dD, v.x); v.y = fmaf(rD.y, dD, v.y);
        v.z = fmaf(rD.z, dD, v.z); v.w = fmaf(rD.w, dD, v.w);
    }
    for (; j < s1; j++) {
        int s = __ldg(&sorted[j]);
        float ds = __ldg(&dinv[s]);
        float4 r = __ldg(reinterpret_cast<const float4*>(x + (size_t)s * DIN) + lane);
        v.x = fmaf(r.x, ds, v.x); v.y = fmaf(r.y, ds, v.y);
        v.z = fmaf(r.z, ds, v.z); v.w = fmaf(r.w, ds, v.w);
    }
    v.x *= dd; v.y *= dd; v.z *= dd; v.w *= dd;
    *(reinterpret_cast<float4*>(z + (size_t)d * DIN) + lane) = v;
}

// ---------------------------------------------------------------------------
// Gather layer 2 (256-dim, pre-scaled inputs), TWO warps per node, unrolled x4
// ---------------------------------------------------------------------------
__global__ void __launch_bounds__(256)
gather_h_kernel(const float* __restrict__ hs, const int* __restrict__ off,
                const int* __restrict__ sorted, const float* __restrict__ dinv,
                float* __restrict__ z, int n) {
    int gwarp = (blockIdx.x * blockDim.x + threadIdx.x) >> 5;
    int lane  = threadIdx.x & 31;
    int d     = gwarp >> 1;
    if (d >= n) return;
    const int foff = ((gwarp & 1) << 5) + lane;
    const int s0 = off[d];
    const int s1 = off[d + 1];

    const float4* base = reinterpret_cast<const float4*>(hs);
    float4 v = __ldg(base + (size_t)d * 64 + foff);

    int j = s0;
    for (; j + 3 < s1; j += 4) {
        int sA = __ldg(&sorted[j]);
        int sB = __ldg(&sorted[j + 1]);
        int sC = __ldg(&sorted[j + 2]);
        int sD = __ldg(&sorted[j + 3]);
        float4 a = __ldg(base + (size_t)sA * 64 + foff);
        float4 b = __ldg(base + (size_t)sB * 64 + foff);
        float4 c = __ldg(base + (size_t)sC * 64 + foff);
        float4 e = __ldg(base + (size_t)sD * 64 + foff);
        v.x += (a.x + b.x) + (c.x + e.x);
        v.y += (a.y + b.y) + (c.y + e.y);
        v.z += (a.z + b.z) + (c.z + e.z);
        v.w += (a.w + b.w) + (c.w + e.w);
    }
    for (; j < s1; j++) {
        int s = __ldg(&sorted[j]);
        float4 a = __ldg(base + (size_t)s * 64 + foff);
        v.x += a.x; v.y += a.y; v.z += a.z; v.w += a.w;
    }

    const float dd = dinv[d];
    v.x *= dd; v.y *= dd; v.z *= dd; v.w *= dd;
    reinterpret_cast<float4*>(z)[(size_t)d * 64 + foff] = v;
}

// ---------------------------------------------------------------------------
// Launch
// ---------------------------------------------------------------------------
extern "C" void kernel_launch(void* const* d_in, const int* in_sizes, int n_in,
                              void* d_out, int out_size) {
    const float* x  = (const float*)d_in[0];
    const int*   ei = (const int*)d_in[1];
    const float* W1 = (const float*)d_in[2];
    const float* b1 = (const float*)d_in[3];
    const float* W2 = (const float*)d_in[4];
    const float* b2 = (const float*)d_in[5];
    float* out = (float*)d_out;

    const int n = in_sizes[0] / DIN;
    const int e = in_sizes[1] / 2;
    const int* esrc = ei;
    const int* edst = ei + e;

    float *dinv, *buf1, *buf2;
    int *cnt, *off, *cur, *srt;
    cudaGetSymbolAddress((void**)&dinv, g_dinv);
    cudaGetSymbolAddress((void**)&buf1, g_buf1);
    cudaGetSymbolAddress((void**)&buf2, g_buf2);
    cudaGetSymbolAddress((void**)&cnt,  g_cnt);
    cudaGetSymbolAddress((void**)&off,  g_off);
    cudaGetSymbolAddress((void**)&cur,  g_cur);
    cudaGetSymbolAddress((void**)&srt,  g_src);

    cudaFuncSetAttribute(gemm_mma_kernel<DIN, 0>, cudaFuncAttributeMaxDynamicSharedMemorySize, GEMM_SMEM);
    cudaFuncSetAttribute(gemm_mma_kernel<DH, 1>,  cudaFuncAttributeMaxDynamicSharedMemorySize, GEMM_SMEM);

    const int T = 256;
    const int e_blk  = (e + T - 1) / T;
    const int gx_blk = (n + (T / 32) - 1) / (T / 32);
    const int gh_blk = (2 * n + (T / 32) - 1) / (T / 32);
    const int gemm_blk = (n + BM - 1) / BM;

    // ----- CSR build -----
    cudaMemsetAsync(cnt, 0, (size_t)n * sizeof(int));
    count_kernel<<<e_blk, T>>>(edst, e, cnt);
    scan_kernel<<<1, 1024>>>(cnt, off, cur, dinv, n);
    fill_kernel<<<e_blk, T>>>(esrc, edst, e, cur, srt);

    // ----- Layer 1 (aggregate-first: 128-dim gather) -----
    gather_x_kernel<<<gx_blk, T>>>(x, off, srt, dinv, buf1, n);
    gemm_mma_kernel<DIN, 0><<<gemm_blk, T, GEMM_SMEM>>>(buf1, W1, dinv, b1, buf2, n);

    // ----- Layer 2 (aggregate-then-transform) -----
    gather_h_kernel<<<gh_blk, T>>>(buf2, off, srt, dinv, buf1, n);
    gemm_mma_kernel<DH, 1><<<gemm_blk, T, GEMM_SMEM>>>(buf1, W2, dinv, b2, out, n);
}

// round 13
// speedup vs baseline: 1.2499x; 1.0108x over previous
#include <cuda_runtime.h>
#include <cuda_bf16.h>
#include <cstdint>

#define MAXN  100000
#define MAXE  2000000
#define DH    256
#define DIN   128

// Scratch (static device globals — no allocation allowed)
__device__ float g_dinv[MAXN];
__device__ float g_buf1[(size_t)MAXN * DH];
__device__ float g_buf2[(size_t)MAXN * DH];
__device__ int   g_cnt[MAXN];
__device__ int   g_off[MAXN + 1];
__device__ int   g_cur[MAXN];
__device__ int   g_src[MAXE];
__device__ float g_wt1[DH * DIN];   // W1^T [256][128]
__device__ float g_wt2[DH * DH];    // W2^T [256][256]

// ---------------------------------------------------------------------------
// CSR build
// ---------------------------------------------------------------------------
__global__ void count_kernel(const int* __restrict__ edst, int e, int* __restrict__ cnt) {
    int i = blockIdx.x * blockDim.x + threadIdx.x;
    if (i < e) atomicAdd(&cnt[edst[i]], 1);
}

__global__ void __launch_bounds__(1024)
scan_kernel(const int* __restrict__ cnt, int* __restrict__ off, int* __restrict__ cur,
            float* __restrict__ dinv, int n) {
    __shared__ int ssum[1024];
    const int tid = threadIdx.x;
    const int chunk = (n + 1023) >> 10;
    const int begin = tid * chunk;
    const int end   = min(begin + chunk, n);

    int mysum = 0;
    for (int i = begin; i < end; i++) mysum += cnt[i];
    ssum[tid] = mysum;
    __syncthreads();
    for (int d = 1; d < 1024; d <<= 1) {
        int add = (tid >= d) ? ssum[tid - d] : 0;
        __syncthreads();
        ssum[tid] += add;
        __syncthreads();
    }
    int run = ssum[tid] - mysum;
    for (int i = begin; i < end; i++) {
        int c = cnt[i];
        off[i] = run;
        cur[i] = run;
        dinv[i] = rsqrtf(1.0f + (float)c);
        run += c;
    }
    if (tid == 1023) off[n] = ssum[1023];
}

__global__ void fill_kernel(const int* __restrict__ esrc, const int* __restrict__ edst,
                            int e, int* __restrict__ cur, int* __restrict__ sorted) {
    int i = blockIdx.x * blockDim.x + threadIdx.x;
    if (i < e) {
        int d = edst[i];
        int pos = atomicAdd(&cur[d], 1);
        sorted[pos] = esrc[i];
    }
}

// ---------------------------------------------------------------------------
// Transpose W [K][256] -> Wt [256][K]
// ---------------------------------------------------------------------------
template <int K>
__global__ void transpose_kernel(const float* __restrict__ W, float* __restrict__ Wt) {
    __shared__ float t[32][33];
    int bx = blockIdx.x * 32;   // N dim
    int by = blockIdx.y * 32;   // K dim
#pragma unroll
    for (int i = 0; i < 4; i++)
        t[threadIdx.y + i * 8][threadIdx.x] =
            W[(size_t)(by + threadIdx.y + i * 8) * DH + bx + threadIdx.x];
    __syncthreads();
#pragma unroll
    for (int i = 0; i < 4; i++)
        Wt[(size_t)(bx + threadIdx.y + i * 8) * K + by + threadIdx.x] =
            t[threadIdx.x][threadIdx.y + i * 8];
}

// ---------------------------------------------------------------------------
// bf16 split helpers (3-term split: x = hi + lo + O(2^-18 x))
// ---------------------------------------------------------------------------
__device__ __forceinline__ uint32_t bpack(__nv_bfloat16 a, __nv_bfloat16 b) {
    __nv_bfloat162 p(a, b);   // a -> lower half, b -> upper half
    return *reinterpret_cast<uint32_t*>(&p);
}
// split pair (f0=k even, f1=k+1) into one hi word + one lo word
__device__ __forceinline__ void split2(float f0, float f1, uint32_t& h, uint32_t& l) {
    __nv_bfloat16 h0 = __float2bfloat16(f0);
    __nv_bfloat16 h1 = __float2bfloat16(f1);
    __nv_bfloat16 l0 = __float2bfloat16(f0 - __bfloat162float(h0));
    __nv_bfloat16 l1 = __float2bfloat16(f1 - __bfloat162float(h1));
    h = bpack(h0, h1);
    l = bpack(l0, l1);
}

__device__ __forceinline__ void mma_bf16(float* c, const uint32_t* a, uint32_t b0, uint32_t b1) {
    asm volatile(
        "mma.sync.aligned.m16n8k16.row.col.f32.bf16.bf16.f32 "
        "{%0,%1,%2,%3}, {%4,%5,%6,%7}, {%8,%9}, {%0,%1,%2,%3};"
        : "+f"(c[0]), "+f"(c[1]), "+f"(c[2]), "+f"(c[3])
        : "r"(a[0]), "r"(a[1]), "r"(a[2]), "r"(a[3]), "r"(b0), "r"(b1));
}

// ---------------------------------------------------------------------------
// Tensor-core GEMM: bf16 m16n8k16 + 3-term split, fragment-layout smem.
//   MODE 0: C = dinv[m] * relu(acc + b);  MODE 1: C = relu(acc + b)
// BM=64, BN=256(full), BK=16; 256 threads = 8 warps (2x4), warp tile 32x64.
// Smem holds PACKED bf16x2 words keyed [row][kpair], stride 12 (conflict-free
// fragment LDS.32: bank = 12*g + t, distinct across the warp).
// Double-buffered; tiles staged via LDG->regs, split once at STS. 1 sync/iter.
// ---------------------------------------------------------------------------
#define BMM     64
#define KPS     12                      // padded kpair stride (8 data + 4 pad)
#define A_WORDS (64 * KPS)              // 768 per buffer
#define B_WORDS (256 * KPS)             // 3072 per buffer
#define BMMA_SMEM ((2 * A_WORDS * 2 + 2 * B_WORDS * 2) * 4)   // 61440 B

template <int K, int MODE>
__global__ void __launch_bounds__(256, 2)
gemm_bmma_kernel(const float* __restrict__ A, const float* __restrict__ Wt,
                 const float* __restrict__ dinv, const float* __restrict__ bias,
                 float* __restrict__ C, int M) {
    constexpr int NT = K / 16;
    extern __shared__ uint32_t smw[];
    uint32_t* AsH = smw;                         // [2][64][KPS]
    uint32_t* AsL = smw + 2 * A_WORDS;
    uint32_t* BsH = smw + 4 * A_WORDS;           // [2][256][KPS]
    uint32_t* BsL = BsH + 2 * B_WORDS;

    const int tid  = threadIdx.x;
    const int bm   = blockIdx.x * BMM;
    const int wid  = tid >> 5;
    const int lane = tid & 31;
    const int wm   = wid >> 2;     // 0..1
    const int wn   = wid & 3;      // 0..3
    const int g    = lane >> 2;    // 0..7
    const int t    = lane & 3;     // 0..3

    // A staging: thread -> (row = tid>>2, k-chunk of 4 at (tid&3)*4)
    const int arow = tid >> 2;
    const int akc  = (tid & 3) * 4;
    const bool aok = (bm + arow) < M;
    const float* aP = &A[(size_t)(bm + arow) * K + akc];
    // B staging: thread -> n = tid, 16 k-floats per tile
    const float* bP = &Wt[(size_t)tid * K];

    float acc[2][8][4];
#pragma unroll
    for (int i = 0; i < 2; i++)
#pragma unroll
        for (int j = 0; j < 8; j++)
#pragma unroll
            for (int q = 0; q < 4; q++) acc[i][j][q] = 0.0f;

    float4 aS;
    float4 bS[4];

    // ---- prologue: LDG + STS tile 0 into buf 0 ----
    aS = aok ? *reinterpret_cast<const float4*>(aP) : make_float4(0.f, 0.f, 0.f, 0.f);
#pragma unroll
    for (int j = 0; j < 4; j++) bS[j] = *reinterpret_cast<const float4*>(bP + j * 4);
    {
        uint32_t hA, lA, hB, lB;
        split2(aS.x, aS.y, hA, lA);
        split2(aS.z, aS.w, hB, lB);
        const int ab = arow * KPS + (akc >> 1);
        *reinterpret_cast<uint2*>(&AsH[ab]) = make_uint2(hA, hB);
        *reinterpret_cast<uint2*>(&AsL[ab]) = make_uint2(lA, lB);
#pragma unroll
        for (int j = 0; j < 4; j++) {
            split2(bS[j].x, bS[j].y, hA, lA);
            split2(bS[j].z, bS[j].w, hB, lB);
            const int bb = tid * KPS + j * 2;
            *reinterpret_cast<uint2*>(&BsH[bb]) = make_uint2(hA, hB);
            *reinterpret_cast<uint2*>(&BsL[bb]) = make_uint2(lA, lB);
        }
    }
    __syncthreads();

    for (int tt = 0; tt < NT; tt++) {
        const int cb  = tt & 1;
        const int nxb = cb ^ 1;
        const bool has_next = (tt + 1 < NT);

        if (has_next) {
            const int k0 = (tt + 1) * 16;
            aS = aok ? *reinterpret_cast<const float4*>(aP + k0)
                     : make_float4(0.f, 0.f, 0.f, 0.f);
#pragma unroll
            for (int j = 0; j < 4; j++)
                bS[j] = *reinterpret_cast<const float4*>(bP + k0 + j * 4);
        }

        // ---- compute on buf cb ----
        const uint32_t* ah = AsH + cb * A_WORDS;
        const uint32_t* al = AsL + cb * A_WORDS;
        const uint32_t* bh = BsH + cb * B_WORDS;
        const uint32_t* bl = BsL + cb * B_WORDS;

        uint32_t aHf[2][4], aLf[2][4];
#pragma unroll
        for (int mt = 0; mt < 2; mt++) {
            const int r0 = (wm * 32 + mt * 16 + g) * KPS;
            aHf[mt][0] = ah[r0 + t];
            aHf[mt][1] = ah[r0 + 8 * KPS + t];
            aHf[mt][2] = ah[r0 + t + 4];
            aHf[mt][3] = ah[r0 + 8 * KPS + t + 4];
            aLf[mt][0] = al[r0 + t];
            aLf[mt][1] = al[r0 + 8 * KPS + t];
            aLf[mt][2] = al[r0 + t + 4];
            aLf[mt][3] = al[r0 + 8 * KPS + t + 4];
        }
#pragma unroll
        for (int nt = 0; nt < 8; nt++) {
            const int nbi = (wn * 64 + nt * 8 + g) * KPS;
            const uint32_t b0H = bh[nbi + t];
            const uint32_t b1H = bh[nbi + t + 4];
            const uint32_t b0L = bl[nbi + t];
            const uint32_t b1L = bl[nbi + t + 4];
#pragma unroll
            for (int mt = 0; mt < 2; mt++) {
                mma_bf16(acc[mt][nt], aHf[mt], b0L, b1L);   // cross terms
                mma_bf16(acc[mt][nt], aLf[mt], b0H, b1H);
                mma_bf16(acc[mt][nt], aHf[mt], b0H, b1H);   // main term
            }
        }

        if (has_next) {
            // ---- STS tile tt+1 into buf nxb ----
            uint32_t hA, lA, hB, lB;
            split2(aS.x, aS.y, hA, lA);
            split2(aS.z, aS.w, hB, lB);
            const int ab = nxb * A_WORDS + arow * KPS + (akc >> 1);
            *reinterpret_cast<uint2*>(&AsH[ab]) = make_uint2(hA, hB);
            *reinterpret_cast<uint2*>(&AsL[ab]) = make_uint2(lA, lB);
#pragma unroll
            for (int j = 0; j < 4; j++) {
                split2(bS[j].x, bS[j].y, hA, lA);
                split2(bS[j].z, bS[j].w, hB, lB);
                const int bb = nxb * B_WORDS + tid * KPS + j * 2;
                *reinterpret_cast<uint2*>(&BsH[bb]) = make_uint2(hA, hB);
                *reinterpret_cast<uint2*>(&BsL[bb]) = make_uint2(lA, lB);
            }
            __syncthreads();
        }
    }

    // ---- epilogue ----
#pragma unroll
    for (int mt = 0; mt < 2; mt++) {
        const int r0 = bm + wm * 32 + mt * 16 + g;
        const int r1 = r0 + 8;
        float s0 = 1.0f, s1 = 1.0f;
        if (MODE == 0) {
            if (r0 < M) s0 = dinv[r0];
            if (r1 < M) s1 = dinv[r1];
        }
#pragma unroll
        for (int nt = 0; nt < 8; nt++) {
            const int c0 = wn * 64 + nt * 8 + 2 * t;
            const float bb0 = bias[c0];
            const float bb1 = bias[c0 + 1];
            float v00 = fmaxf(acc[mt][nt][0] + bb0, 0.0f) * s0;
            float v01 = fmaxf(acc[mt][nt][1] + bb1, 0.0f) * s0;
            float v10 = fmaxf(acc[mt][nt][2] + bb0, 0.0f) * s1;
            float v11 = fmaxf(acc[mt][nt][3] + bb1, 0.0f) * s1;
            if (r0 < M)
                *reinterpret_cast<float2*>(&C[(size_t)r0 * DH + c0]) = make_float2(v00, v01);
            if (r1 < M)
                *reinterpret_cast<float2*>(&C[(size_t)r1 * DH + c0]) = make_float2(v10, v11);
        }
    }
}

// ---------------------------------------------------------------------------
// Gather layer 1 (128-dim raw features), unrolled x4
// ---------------------------------------------------------------------------
__global__ void __launch_bounds__(256)
gather_x_kernel(const float* __restrict__ x, const int* __restrict__ off,
                const int* __restrict__ sorted, const float* __restrict__ dinv,
                float* __restrict__ z, int n) {
    int warp = (blockIdx.x * blockDim.x + threadIdx.x) >> 5;
    int lane = threadIdx.x & 31;
    if (warp >= n) return;
    const int d  = warp;
    const int s0 = off[d];
    const int s1 = off[d + 1];
    const float dd = dinv[d];

    float4 a = __ldg(reinterpret_cast<const float4*>(x + (size_t)d * DIN) + lane);
    float4 v = make_float4(a.x * dd, a.y * dd, a.z * dd, a.w * dd);

    int j = s0;
    for (; j + 3 < s1; j += 4) {
        int sA = __ldg(&sorted[j]);
        int sB = __ldg(&sorted[j + 1]);
        int sC = __ldg(&sorted[j + 2]);
        int sD = __ldg(&sorted[j + 3]);
        float dA = __ldg(&dinv[sA]);
        float dB = __ldg(&dinv[sB]);
        float dC = __ldg(&dinv[sC]);
        float dD = __ldg(&dinv[sD]);
        float4 rA = __ldg(reinterpret_cast<const float4*>(x + (size_t)sA * DIN) + lane);
        float4 rB = __ldg(reinterpret_cast<const float4*>(x + (size_t)sB * DIN) + lane);
        float4 rC = __ldg(reinterpret_cast<const float4*>(x + (size_t)sC * DIN) + lane);
        float4 rD = __ldg(reinterpret_cast<const float4*>(x + (size_t)sD * DIN) + lane);
        v.x = fmaf(rA.x, dA, v.x); v.y = fmaf(rA.y, dA, v.y);
        v.z = fmaf(rA.z, dA, v.z); v.w = fmaf(rA.w, dA, v.w);
        v.x = fmaf(rB.x, dB, v.x); v.y = fmaf(rB.y, dB, v.y);
        v.z = fmaf(rB.z, dB, v.z); v.w = fmaf(rB.w, dB, v.w);
        v.x = fmaf(rC.x, dC, v.x); v.y = fmaf(rC.y, dC, v.y);
        v.z = fmaf(rC.z, dC, v.z); v.w = fmaf(rC.w, dC, v.w);
        v.x = fmaf(rD.x, dD, v.x); v.y = fmaf(rD.y, dD, v.y);
        v.z = fmaf(rD.z, dD, v.z); v.w = fmaf(rD.w, dD, v.w);
    }
    for (; j < s1; j++) {
        int s = __ldg(&sorted[j]);
        float ds = __ldg(&dinv[s]);
        float4 r = __ldg(reinterpret_cast<const float4*>(x + (size_t)s * DIN) + lane);
        v.x = fmaf(r.x, ds, v.x); v.y = fmaf(r.y, ds, v.y);
        v.z = fmaf(r.z, ds, v.z); v.w = fmaf(r.w, ds, v.w);
    }
    v.x *= dd; v.y *= dd; v.z *= dd; v.w *= dd;
    *(reinterpret_cast<float4*>(z + (size_t)d * DIN) + lane) = v;
}

// ---------------------------------------------------------------------------
// Gather layer 2 (256-dim, pre-scaled inputs), TWO warps per node, unrolled x4
// ---------------------------------------------------------------------------
__global__ void __launch_bounds__(256)
gather_h_kernel(const float* __restrict__ hs, const int* __restrict__ off,
                const int* __restrict__ sorted, const float* __restrict__ dinv,
                float* __restrict__ z, int n) {
    int gwarp = (blockIdx.x * blockDim.x + threadIdx.x) >> 5;
    int lane  = threadIdx.x & 31;
    int d     = gwarp >> 1;
    if (d >= n) return;
    const int foff = ((gwarp & 1) << 5) + lane;
    const int s0 = off[d];
    const int s1 = off[d + 1];

    const float4* base = reinterpret_cast<const float4*>(hs);
    float4 v = __ldg(base + (size_t)d * 64 + foff);

    int j = s0;
    for (; j + 3 < s1; j += 4) {
        int sA = __ldg(&sorted[j]);
        int sB = __ldg(&sorted[j + 1]);
        int sC = __ldg(&sorted[j + 2]);
        int sD = __ldg(&sorted[j + 3]);
        float4 a = __ldg(base + (size_t)sA * 64 + foff);
        float4 b = __ldg(base + (size_t)sB * 64 + foff);
        float4 c = __ldg(base + (size_t)sC * 64 + foff);
        float4 e = __ldg(base + (size_t)sD * 64 + foff);
        v.x += (a.x + b.x) + (c.x + e.x);
        v.y += (a.y + b.y) + (c.y + e.y);
        v.z += (a.z + b.z) + (c.z + e.z);
        v.w += (a.w + b.w) + (c.w + e.w);
    }
    for (; j < s1; j++) {
        int s = __ldg(&sorted[j]);
        float4 a = __ldg(base + (size_t)s * 64 + foff);
        v.x += a.x; v.y += a.y; v.z += a.z; v.w += a.w;
    }

    const float dd = dinv[d];
    v.x *= dd; v.y *= dd; v.z *= dd; v.w *= dd;
    reinterpret_cast<float4*>(z)[(size_t)d * 64 + foff] = v;
}

// ---------------------------------------------------------------------------
// Launch
// ---------------------------------------------------------------------------
extern "C" void kernel_launch(void* const* d_in, const int* in_sizes, int n_in,
                              void* d_out, int out_size) {
    const float* x  = (const float*)d_in[0];
    const int*   ei = (const int*)d_in[1];
    const float* W1 = (const float*)d_in[2];
    const float* b1 = (const float*)d_in[3];
    const float* W2 = (const float*)d_in[4];
    const float* b2 = (const float*)d_in[5];
    float* out = (float*)d_out;

    const int n = in_sizes[0] / DIN;
    const int e = in_sizes[1] / 2;
    const int* esrc = ei;
    const int* edst = ei + e;

    float *dinv, *buf1, *buf2, *wt1, *wt2;
    int *cnt, *off, *cur, *srt;
    cudaGetSymbolAddress((void**)&dinv, g_dinv);
    cudaGetSymbolAddress((void**)&buf1, g_buf1);
    cudaGetSymbolAddress((void**)&buf2, g_buf2);
    cudaGetSymbolAddress((void**)&cnt,  g_cnt);
    cudaGetSymbolAddress((void**)&off,  g_off);
    cudaGetSymbolAddress((void**)&cur,  g_cur);
    cudaGetSymbolAddress((void**)&srt,  g_src);
    cudaGetSymbolAddress((void**)&wt1,  g_wt1);
    cudaGetSymbolAddress((void**)&wt2,  g_wt2);

    cudaFuncSetAttribute(gemm_bmma_kernel<DIN, 0>, cudaFuncAttributeMaxDynamicSharedMemorySize, BMMA_SMEM);
    cudaFuncSetAttribute(gemm_bmma_kernel<DH, 1>,  cudaFuncAttributeMaxDynamicSharedMemorySize, BMMA_SMEM);

    const int T = 256;
    const int e_blk  = (e + T - 1) / T;
    const int gx_blk = (n + (T / 32) - 1) / (T / 32);
    const int gh_blk = (2 * n + (T / 32) - 1) / (T / 32);
    const int gemm_blk = (n + BMM - 1) / BMM;

    // ----- CSR build -----
    cudaMemsetAsync(cnt, 0, (size_t)n * sizeof(int));
    count_kernel<<<e_blk, T>>>(edst, e, cnt);
    scan_kernel<<<1, 1024>>>(cnt, off, cur, dinv, n);
    fill_kernel<<<e_blk, T>>>(esrc, edst, e, cur, srt);

    // ----- weight transposes -----
    transpose_kernel<DIN><<<dim3(DH / 32, DIN / 32), dim3(32, 8)>>>(W1, wt1);
    transpose_kernel<DH><<<dim3(DH / 32, DH / 32), dim3(32, 8)>>>(W2, wt2);

    // ----- Layer 1 (aggregate-first: 128-dim gather) -----
    gather_x_kernel<<<gx_blk, T>>>(x, off, srt, dinv, buf1, n);
    gemm_bmma_kernel<DIN, 0><<<gemm_blk, T, BMMA_SMEM>>>(buf1, wt1, dinv, b1, buf2, n);

    // ----- Layer 2 (aggregate-then-transform) -----
    gather_h_kernel<<<gh_blk, T>>>(buf2, off, srt, dinv, buf1, n);
    gemm_bmma_kernel<DH, 1><<<gemm_blk, T, BMMA_SMEM>>>(buf1, wt2, dinv, b2, out, n);
}